// round 8
// baseline (speedup 1.0000x reference)
#include <cuda_runtime.h>
#include <cuda_bf16.h>
#include <math.h>
#include <stdint.h>

#define N_NODES 50000
#define N_EDGES 500000
#define D 128
#define BN_EPS 1e-5f

// ---------------- scratch (static device globals; no allocation) ----------------
__device__ float g_P[(size_t)N_NODES * 512];     // [PF1|PF2|PS1|PS2] per node
__device__ float g_agg[(size_t)N_NODES * D];     // scatter-sum target
__device__ float g_B1[128 * 512];                // repacked node weights (fp32)
__device__ float g_stats[2 * D];                 // [sum | sumsq]
// B fragments for mma.sync m16n8k16 (bf16), fragment-linear:
// u32 index = ((((term*8 + kstep)*32 + ntile)*32) + lane)*2 + reg
// term 0 = hi, term 1 = lo. B logical: [k=128][n=256], n=2c -> Wf[256+k][c], n=2c+1 -> Ws[256+k][c]
__device__ __align__(16) uint32_t g_Bfrag[2 * 8 * 32 * 32 * 2];   // 128 KB

// ---------------- weight repack ----------------
__global__ void prep_weights(const float* __restrict__ Wf, const float* __restrict__ Ws) {
    int i = blockIdx.x * blockDim.x + threadIdx.x;
    if (i < 128 * 512) {
        int k = i >> 9, j = i & 511;
        float v;
        if (j < 128)      v = Wf[k * 128 + j];
        else if (j < 256) v = Wf[(128 + k) * 128 + (j - 128)];
        else if (j < 384) v = Ws[k * 128 + (j - 256)];
        else              v = Ws[(128 + k) * 128 + (j - 384)];
        g_B1[i] = v;
    }
    if (i < 32768) {
        int reg   = i & 1;
        int lane  = (i >> 1) & 31;
        int ntile = (i >> 6) & 31;
        int kstep = (i >> 11) & 7;
        int term  = (i >> 14) & 1;
        int k0 = kstep * 16 + (lane & 3) * 2 + reg * 8;
        int n  = ntile * 8 + (lane >> 2);
        int c  = n >> 1;
        const float* W = (n & 1) ? Ws : Wf;
        float v0 = W[(256 + k0) * 128 + c];
        float v1 = W[(256 + k0 + 1) * 128 + c];
        __nv_bfloat16 h0 = __float2bfloat16_rn(v0);
        __nv_bfloat16 h1 = __float2bfloat16_rn(v1);
        uint32_t out;
        if (term == 0) {
            out = (uint32_t)__bfloat16_as_ushort(h0) | ((uint32_t)__bfloat16_as_ushort(h1) << 16);
        } else {
            __nv_bfloat16 l0 = __float2bfloat16_rn(v0 - __bfloat162float(h0));
            __nv_bfloat16 l1 = __float2bfloat16_rn(v1 - __bfloat162float(h1));
            out = (uint32_t)__bfloat16_as_ushort(l0) | ((uint32_t)__bfloat16_as_ushort(l1) << 16);
        }
        g_Bfrag[i] = out;
    }
}

// ---------------- zero scratch ----------------
__global__ void zero_scratch() {
    size_t n4 = (size_t)N_NODES * D / 4;
    float4* p = reinterpret_cast<float4*>(g_agg);
    for (size_t i = blockIdx.x * blockDim.x + threadIdx.x; i < n4; i += (size_t)gridDim.x * blockDim.x)
        p[i] = make_float4(0.f, 0.f, 0.f, 0.f);
    int t = blockIdx.x * blockDim.x + threadIdx.x;
    if (t < 2 * D) g_stats[t] = 0.f;
}

// ---------------- node SGEMM: g_P[M,512] = x[M,128] @ g_B1[128,512] ----------------
#define BM 64
#define BN 64
#define BK 16
__global__ __launch_bounds__(256) void node_gemm(const float* __restrict__ A, int M)
{
    const float* __restrict__ B = g_B1;
    float* __restrict__ C = g_P;
    const int N = 512;
    __shared__ float As[BK][BM];
    __shared__ float Bs[BK][BN];
    const int tid = threadIdx.x;
    const int row0 = blockIdx.y * BM;
    const int col0 = blockIdx.x * BN;
    const int tr = tid >> 4, tc = tid & 15;
    const int a_r = tid >> 2, a_c4 = (tid & 3) * 4;
    const int b_r = tid >> 4, b_c4 = (tid & 15) * 4;
    float acc[4][4];
#pragma unroll
    for (int i = 0; i < 4; i++)
#pragma unroll
        for (int j = 0; j < 4; j++) acc[i][j] = 0.f;
    const int ar = row0 + a_r;
    for (int k0 = 0; k0 < 128; k0 += BK) {
        float4 av = make_float4(0.f, 0.f, 0.f, 0.f);
        if (ar < M) av = *reinterpret_cast<const float4*>(A + (size_t)ar * 128 + k0 + a_c4);
        As[a_c4 + 0][a_r] = av.x; As[a_c4 + 1][a_r] = av.y;
        As[a_c4 + 2][a_r] = av.z; As[a_c4 + 3][a_r] = av.w;
        float4 bv = *reinterpret_cast<const float4*>(B + (size_t)(k0 + b_r) * N + col0 + b_c4);
        *reinterpret_cast<float4*>(&Bs[b_r][b_c4]) = bv;
        __syncthreads();
#pragma unroll
        for (int k = 0; k < BK; k++) {
            float4 a = *reinterpret_cast<float4*>(&As[k][tr * 4]);
            float4 b = *reinterpret_cast<float4*>(&Bs[k][tc * 4]);
            acc[0][0] += a.x * b.x; acc[0][1] += a.x * b.y; acc[0][2] += a.x * b.z; acc[0][3] += a.x * b.w;
            acc[1][0] += a.y * b.x; acc[1][1] += a.y * b.y; acc[1][2] += a.y * b.z; acc[1][3] += a.y * b.w;
            acc[2][0] += a.z * b.x; acc[2][1] += a.z * b.y; acc[2][2] += a.z * b.z; acc[2][3] += a.z * b.w;
            acc[3][0] += a.w * b.x; acc[3][1] += a.w * b.y; acc[3][2] += a.w * b.z; acc[3][3] += a.w * b.w;
        }
        __syncthreads();
    }
#pragma unroll
    for (int i = 0; i < 4; i++) {
        int row = row0 + tr * 4 + i;
        if (row < M) {
            float4 v = make_float4(acc[i][0], acc[i][1], acc[i][2], acc[i][3]);
            *reinterpret_cast<float4*>(C + (size_t)row * N + col0 + tc * 4) = v;
        }
    }
}

// ---------------- activations ----------------
__device__ __forceinline__ float sigmoidf_(float x) { return 1.f / (1.f + expf(-x)); }
__device__ __forceinline__ float softplusf_(float x) {
    return fmaxf(x, 0.f) + log1pf(expf(-fabsf(x)));
}

__device__ __forceinline__ void mma_bf16(float* d, uint32_t a0, uint32_t a1, uint32_t a2,
                                         uint32_t a3, uint32_t b0, uint32_t b1) {
    asm volatile(
        "mma.sync.aligned.m16n8k16.row.col.f32.bf16.bf16.f32 "
        "{%0,%1,%2,%3}, {%4,%5,%6,%7}, {%8,%9}, {%0,%1,%2,%3};"
        : "+f"(d[0]), "+f"(d[1]), "+f"(d[2]), "+f"(d[3])
        : "r"(a0), "r"(a1), "r"(a2), "r"(a3), "r"(b0), "r"(b1));
}
__device__ __forceinline__ void ldsm_x4(uint32_t& a0, uint32_t& a1, uint32_t& a2, uint32_t& a3,
                                        uint32_t saddr) {
    asm volatile("ldmatrix.sync.aligned.m8n8.x4.shared.b16 {%0,%1,%2,%3}, [%4];"
                 : "=r"(a0), "=r"(a1), "=r"(a2), "=r"(a3) : "r"(saddr));
}
__device__ __forceinline__ uint32_t smem_u32(const void* p) {
    uint32_t a;
    asm("{ .reg .u64 t; cvta.to.shared.u64 t, %1; cvt.u32.u64 %0, t; }" : "=r"(a) : "l"(p));
    return a;
}

// ---------------- fused edge GEMM (mma.sync bf16-split, col-halved CTAs) ----------------
// CTA: 256 threads, 64 edges x 128 interleaved cols (half h = blockIdx.y; orig cols [h*64, h*64+64)).
// Warps: warpM = wid&1 (32 rows), warpN = wid>>1 (32 interleaved cols = 4 ntiles).
// smem: [0,256) src, [256,512) tgt,
//       A hi [512, 17920) 64x272B,  A lo [17920, 35328),
//       B slice [35328, 100864) = 64 KB (this half's ntiles, fragment-linear).
//       D overlay at 512: 64 x 132 fp32 (33792 B; fits in A region).
#define SM_SRC 0
#define SM_TGT 256
#define SM_AHI 512
#define SM_ALO (512 + 64 * 272)
#define SM_B   (512 + 2 * 64 * 272)
#define SM_D   512
#define DSTRIDE 132
#define EDGE_SMEM (SM_B + 65536)

__global__ __launch_bounds__(256, 2) void edge_fused_mma(
    const float* __restrict__ A,
    const int* __restrict__ src, const int* __restrict__ tgt,
    const float* __restrict__ bf, const float* __restrict__ bs)
{
    extern __shared__ char basep[];
    const uint32_t sbase = smem_u32(basep);
    const int tid = threadIdx.x;
    const int wid = tid >> 5;
    const int lane = tid & 31;
    const int row0 = blockIdx.x * 64;
    const int h = blockIdx.y;          // col half: orig cols [h*64, h*64+64)
    const int warpM = wid & 1;         // 32 rows each
    const int warpN = wid >> 1;        // 4 ntiles each (32 interleaved cols)

    int* s_src = reinterpret_cast<int*>(basep + SM_SRC);
    int* s_tgt = reinterpret_cast<int*>(basep + SM_TGT);
    if (tid < 64) {
        int r = row0 + tid;
        s_src[tid] = (r < N_EDGES) ? src[r] : 0;
        s_tgt[tid] = (r < N_EDGES) ? tgt[r] : 0;
    }

    // B slice: 16 (term,kstep) blocks, each 256 int4; this half's 16 ntiles.
    {
        int4* dst = reinterpret_cast<int4*>(basep + SM_B);
        const int4* s = reinterpret_cast<const int4*>(g_Bfrag);
#pragma unroll
        for (int blk = 0; blk < 16; blk++)
            dst[blk * 256 + tid] = s[blk * 512 + h * 256 + tid];
    }

    // A tile: 64x128 fp32 -> bf16 hi/lo smem (row stride 272 B)
    {
        char* ahi = basep + SM_AHI;
        char* alo = basep + SM_ALO;
#pragma unroll
        for (int it = 0; it < 8; it++) {
            int lin = it * 256 + tid;        // float4 over 64x32
            int row = lin >> 5;
            int c4 = (lin & 31) << 2;
            int e = row0 + row;
            float4 v = make_float4(0.f, 0.f, 0.f, 0.f);
            if (e < N_EDGES) v = *reinterpret_cast<const float4*>(A + (size_t)e * 128 + c4);
            __nv_bfloat16 h0 = __float2bfloat16_rn(v.x), h1 = __float2bfloat16_rn(v.y);
            __nv_bfloat16 h2 = __float2bfloat16_rn(v.z), h3 = __float2bfloat16_rn(v.w);
            __nv_bfloat16 l0 = __float2bfloat16_rn(v.x - __bfloat162float(h0));
            __nv_bfloat16 l1 = __float2bfloat16_rn(v.y - __bfloat162float(h1));
            __nv_bfloat16 l2 = __float2bfloat16_rn(v.z - __bfloat162float(h2));
            __nv_bfloat16 l3 = __float2bfloat16_rn(v.w - __bfloat162float(h3));
            uint2 hp, lp;
            hp.x = (uint32_t)__bfloat16_as_ushort(h0) | ((uint32_t)__bfloat16_as_ushort(h1) << 16);
            hp.y = (uint32_t)__bfloat16_as_ushort(h2) | ((uint32_t)__bfloat16_as_ushort(h3) << 16);
            lp.x = (uint32_t)__bfloat16_as_ushort(l0) | ((uint32_t)__bfloat16_as_ushort(l1) << 16);
            lp.y = (uint32_t)__bfloat16_as_ushort(l2) | ((uint32_t)__bfloat16_as_ushort(l3) << 16);
            int off = row * 272 + c4 * 2;
            *reinterpret_cast<uint2*>(ahi + off) = hp;
            *reinterpret_cast<uint2*>(alo + off) = lp;
        }
    }
    __syncthreads();

    float acc[2][4][4];
#pragma unroll
    for (int mt = 0; mt < 2; mt++)
#pragma unroll
        for (int nt = 0; nt < 4; nt++)
#pragma unroll
            for (int j = 0; j < 4; j++) acc[mt][nt][j] = 0.f;

    // mainloop: ldmatrix A frags, smem B frags, 3-term bf16 split
    {
        const uint2* bp = reinterpret_cast<const uint2*>(basep + SM_B);
        const uint32_t a_lane_off = (uint32_t)((lane & 15) * 272 + (lane >> 4) * 16);
#pragma unroll
        for (int kstep = 0; kstep < 8; kstep++) {
            uint2 bh[4], bl[4];
#pragma unroll
            for (int nt = 0; nt < 4; nt++) {
                bh[nt] = bp[(kstep * 16 + warpN * 4 + nt) * 32 + lane];
                bl[nt] = bp[((8 + kstep) * 16 + warpN * 4 + nt) * 32 + lane];
            }
#pragma unroll
            for (int mt = 0; mt < 2; mt++) {
                uint32_t rowbase = (uint32_t)((warpM * 32 + mt * 16) * 272 + kstep * 32);
                uint32_t ah0, ah1, ah2, ah3, al0, al1, al2, al3;
                ldsm_x4(ah0, ah1, ah2, ah3, sbase + SM_AHI + rowbase + a_lane_off);
                ldsm_x4(al0, al1, al2, al3, sbase + SM_ALO + rowbase + a_lane_off);
#pragma unroll
                for (int nt = 0; nt < 4; nt++)
                    mma_bf16(acc[mt][nt], ah0, ah1, ah2, ah3, bh[nt].x, bh[nt].y);
#pragma unroll
                for (int nt = 0; nt < 4; nt++)
                    mma_bf16(acc[mt][nt], al0, al1, al2, al3, bh[nt].x, bh[nt].y);
#pragma unroll
                for (int nt = 0; nt < 4; nt++)
                    mma_bf16(acc[mt][nt], ah0, ah1, ah2, ah3, bl[nt].x, bl[nt].y);
            }
        }
    }
    __syncthreads();   // A region dead; reuse as D staging

    // acc -> smem D [64][DSTRIDE]
    {
        float* Dsm = reinterpret_cast<float*>(basep + SM_D);
#pragma unroll
        for (int mt = 0; mt < 2; mt++) {
            int row = warpM * 32 + mt * 16 + (lane >> 2);
#pragma unroll
            for (int nt = 0; nt < 4; nt++) {
                int col = warpN * 32 + nt * 8 + (lane & 3) * 2;   // interleaved within 128
                float* p0 = Dsm + (size_t)row * DSTRIDE + col;
                p0[0] = acc[mt][nt][0];
                p0[1] = acc[mt][nt][1];
                float* p1 = p0 + 8 * DSTRIDE;
                p1[0] = acc[mt][nt][2];
                p1[1] = acc[mt][nt][3];
            }
        }
    }
    __syncthreads();

    // epilogue: gate + scatter. orig cols c = h*64 + tc*4 .. +3
    {
        const float* Dsm = reinterpret_cast<const float*>(basep + SM_D);
        const int tr = tid >> 4;   // 16 groups x 4 rows
        const int tc = tid & 15;
        const int c0 = h * 64 + tc * 4;
        const float4 bfv = *reinterpret_cast<const float4*>(bf + c0);
        const float4 bsv = *reinterpret_cast<const float4*>(bs + c0);
#pragma unroll
        for (int i = 0; i < 4; i++) {
            int lr = tr * 4 + i;
            int e = row0 + lr;
            if (e >= N_EDGES) break;
            int sN = s_src[lr];
            int tN = s_tgt[lr];
            const float* dp = Dsm + (size_t)lr * DSTRIDE + tc * 8;
            float4 d0 = *reinterpret_cast<const float4*>(dp);       // f0,s0,f1,s1
            float4 d1 = *reinterpret_cast<const float4*>(dp + 4);   // f2,s2,f3,s3

            const float4 pf1 = *reinterpret_cast<const float4*>(g_P + (size_t)sN * 512 + 0   + c0);
            const float4 pf2 = *reinterpret_cast<const float4*>(g_P + (size_t)tN * 512 + 128 + c0);
            const float4 ps1 = *reinterpret_cast<const float4*>(g_P + (size_t)sN * 512 + 256 + c0);
            const float4 ps2 = *reinterpret_cast<const float4*>(g_P + (size_t)tN * 512 + 384 + c0);

            float f0 = d0.x + pf1.x + pf2.x + bfv.x;
            float s0 = d0.y + ps1.x + ps2.x + bsv.x;
            float f1 = d0.z + pf1.y + pf2.y + bfv.y;
            float s1 = d0.w + ps1.y + ps2.y + bsv.y;
            float f2 = d1.x + pf1.z + pf2.z + bfv.z;
            float s2 = d1.y + ps1.z + ps2.z + bsv.z;
            float f3 = d1.z + pf1.w + pf2.w + bfv.w;
            float s3 = d1.w + ps1.w + ps2.w + bsv.w;

            float m0 = sigmoidf_(f0) * softplusf_(s0);
            float m1 = sigmoidf_(f1) * softplusf_(s1);
            float m2 = sigmoidf_(f2) * softplusf_(s2);
            float m3 = sigmoidf_(f3) * softplusf_(s3);

            float* dst = g_agg + (size_t)sN * D + c0;
            asm volatile("red.global.add.v4.f32 [%0], {%1, %2, %3, %4};"
                         :: "l"(dst), "f"(m0), "f"(m1), "f"(m2), "f"(m3) : "memory");
        }
    }
}

// ---------------- BN stats ----------------
__global__ __launch_bounds__(128) void bn_stats() {
    const int d = threadIdx.x;
    float sum = 0.f, sq = 0.f;
    for (int n = blockIdx.x; n < N_NODES; n += gridDim.x) {
        float v = g_agg[(size_t)n * D + d];
        sum += v;
        sq += v * v;
    }
    atomicAdd(&g_stats[d], sum);
    atomicAdd(&g_stats[D + d], sq);
}

// ---------------- BN apply + residual + softplus ----------------
__global__ __launch_bounds__(256) void final_kernel(
    const float* __restrict__ x, const float* __restrict__ gamma,
    const float* __restrict__ beta, float* __restrict__ out)
{
    const float invN = 1.0f / (float)N_NODES;
    for (size_t idx = (size_t)blockIdx.x * blockDim.x + threadIdx.x;
         idx < (size_t)N_NODES * D;
         idx += (size_t)gridDim.x * blockDim.x) {
        int d = (int)(idx & (D - 1));
        float mean = g_stats[d] * invN;
        float var = g_stats[D + d] * invN - mean * mean;
        float rstd = rsqrtf(var + BN_EPS);
        float a = (g_agg[idx] - mean) * rstd * gamma[d] + beta[d];
        out[idx] = softplusf_(x[idx] + a);
    }
}

// ---------------- launch ----------------
extern "C" void kernel_launch(void* const* d_in, const int* in_sizes, int n_in,
                              void* d_out, int out_size) {
    const float* x         = (const float*)d_in[0];
    const float* edge_attr = (const float*)d_in[1];
    const int*   edge_src  = (const int*)d_in[2];
    const int*   edge_tgt  = (const int*)d_in[3];
    const float* Wf        = (const float*)d_in[4];
    const float* bf        = (const float*)d_in[5];
    const float* Ws        = (const float*)d_in[6];
    const float* bs        = (const float*)d_in[7];
    const float* gamma     = (const float*)d_in[8];
    const float* beta      = (const float*)d_in[9];
    float* out = (float*)d_out;

    static bool attr_set = false;
    if (!attr_set) {
        cudaFuncSetAttribute(edge_fused_mma, cudaFuncAttributeMaxDynamicSharedMemorySize, EDGE_SMEM);
        attr_set = true;
    }

    prep_weights<<<256, 256>>>(Wf, Ws);
    zero_scratch<<<4096, 256>>>();
    {
        dim3 grid(512 / BN, (N_NODES + BM - 1) / BM);
        node_gemm<<<grid, 256>>>(x, N_NODES);
    }
    {
        dim3 grid((N_EDGES + 63) / 64, 2);
        edge_fused_mma<<<grid, 256, EDGE_SMEM>>>(edge_attr, edge_src, edge_tgt, bf, bs);
    }
    bn_stats<<<512, 128>>>();
    final_kernel<<<(N_NODES * D + 255) / 256, 256>>>(x, gamma, beta, out);
}

// round 9
// speedup vs baseline: 1.2584x; 1.2584x over previous
#include <cuda_runtime.h>
#include <cuda_bf16.h>
#include <cuda_fp16.h>
#include <math.h>
#include <stdint.h>

#define N_NODES 50000
#define N_EDGES 500000
#define D 128
#define BN_EPS 1e-5f

// ---------------- scratch (static device globals; no allocation) ----------------
__device__ float g_P[(size_t)N_NODES * 512];     // [PF1|PF2|PS1|PS2] per node
__device__ float g_agg[(size_t)N_NODES * D];     // scatter-sum target
__device__ float g_B1[128 * 512];                // repacked node weights (fp32)
__device__ float g_stats[2 * D];                 // [sum | sumsq]
// B fragments for mma.sync m16n8k16 (f16), single hi term, fragment-linear:
// u32 index = (((kstep*32 + ntile)*32) + lane)*2 + reg
// B logical: [k=128][n=256], n=2c -> Wf[256+k][c], n=2c+1 -> Ws[256+k][c]
__device__ __align__(16) uint32_t g_Bfrag[8 * 32 * 32 * 2];   // 64 KB

// ---------------- weight repack ----------------
__global__ void prep_weights(const float* __restrict__ Wf, const float* __restrict__ Ws) {
    int i = blockIdx.x * blockDim.x + threadIdx.x;
    if (i < 128 * 512) {
        int k = i >> 9, j = i & 511;
        float v;
        if (j < 128)      v = Wf[k * 128 + j];
        else if (j < 256) v = Wf[(128 + k) * 128 + (j - 128)];
        else if (j < 384) v = Ws[k * 128 + (j - 256)];
        else              v = Ws[(128 + k) * 128 + (j - 384)];
        g_B1[i] = v;
    }
    if (i < 16384) {
        int reg   = i & 1;
        int lane  = (i >> 1) & 31;
        int ntile = (i >> 6) & 31;
        int kstep = (i >> 11) & 7;
        int k0 = kstep * 16 + (lane & 3) * 2 + reg * 8;
        int n  = ntile * 8 + (lane >> 2);
        int c  = n >> 1;
        const float* W = (n & 1) ? Ws : Wf;
        __half h0 = __float2half_rn(W[(256 + k0) * 128 + c]);
        __half h1 = __float2half_rn(W[(256 + k0 + 1) * 128 + c]);
        g_Bfrag[i] = (uint32_t)__half_as_ushort(h0) | ((uint32_t)__half_as_ushort(h1) << 16);
    }
}

// ---------------- zero scratch ----------------
__global__ void zero_scratch() {
    size_t n4 = (size_t)N_NODES * D / 4;
    float4* p = reinterpret_cast<float4*>(g_agg);
    for (size_t i = blockIdx.x * blockDim.x + threadIdx.x; i < n4; i += (size_t)gridDim.x * blockDim.x)
        p[i] = make_float4(0.f, 0.f, 0.f, 0.f);
    int t = blockIdx.x * blockDim.x + threadIdx.x;
    if (t < 2 * D) g_stats[t] = 0.f;
}

// ---------------- node SGEMM: g_P[M,512] = x[M,128] @ g_B1[128,512] ----------------
#define BM 64
#define BN 64
#define BK 16
__global__ __launch_bounds__(256) void node_gemm(const float* __restrict__ A, int M)
{
    const float* __restrict__ B = g_B1;
    float* __restrict__ C = g_P;
    const int N = 512;
    __shared__ float As[BK][BM];
    __shared__ float Bs[BK][BN];
    const int tid = threadIdx.x;
    const int row0 = blockIdx.y * BM;
    const int col0 = blockIdx.x * BN;
    const int tr = tid >> 4, tc = tid & 15;
    const int a_r = tid >> 2, a_c4 = (tid & 3) * 4;
    const int b_r = tid >> 4, b_c4 = (tid & 15) * 4;
    float acc[4][4];
#pragma unroll
    for (int i = 0; i < 4; i++)
#pragma unroll
        for (int j = 0; j < 4; j++) acc[i][j] = 0.f;
    const int ar = row0 + a_r;
    for (int k0 = 0; k0 < 128; k0 += BK) {
        float4 av = make_float4(0.f, 0.f, 0.f, 0.f);
        if (ar < M) av = *reinterpret_cast<const float4*>(A + (size_t)ar * 128 + k0 + a_c4);
        As[a_c4 + 0][a_r] = av.x; As[a_c4 + 1][a_r] = av.y;
        As[a_c4 + 2][a_r] = av.z; As[a_c4 + 3][a_r] = av.w;
        float4 bv = *reinterpret_cast<const float4*>(B + (size_t)(k0 + b_r) * N + col0 + b_c4);
        *reinterpret_cast<float4*>(&Bs[b_r][b_c4]) = bv;
        __syncthreads();
#pragma unroll
        for (int k = 0; k < BK; k++) {
            float4 a = *reinterpret_cast<float4*>(&As[k][tr * 4]);
            float4 b = *reinterpret_cast<float4*>(&Bs[k][tc * 4]);
            acc[0][0] += a.x * b.x; acc[0][1] += a.x * b.y; acc[0][2] += a.x * b.z; acc[0][3] += a.x * b.w;
            acc[1][0] += a.y * b.x; acc[1][1] += a.y * b.y; acc[1][2] += a.y * b.z; acc[1][3] += a.y * b.w;
            acc[2][0] += a.z * b.x; acc[2][1] += a.z * b.y; acc[2][2] += a.z * b.z; acc[2][3] += a.z * b.w;
            acc[3][0] += a.w * b.x; acc[3][1] += a.w * b.y; acc[3][2] += a.w * b.z; acc[3][3] += a.w * b.w;
        }
        __syncthreads();
    }
#pragma unroll
    for (int i = 0; i < 4; i++) {
        int row = row0 + tr * 4 + i;
        if (row < M) {
            float4 v = make_float4(acc[i][0], acc[i][1], acc[i][2], acc[i][3]);
            *reinterpret_cast<float4*>(C + (size_t)row * N + col0 + tc * 4) = v;
        }
    }
}

// ---------------- activations ----------------
__device__ __forceinline__ float sigmoidf_(float x) { return 1.f / (1.f + expf(-x)); }
__device__ __forceinline__ float softplusf_(float x) {
    return fmaxf(x, 0.f) + log1pf(expf(-fabsf(x)));
}

__device__ __forceinline__ void mma_f16(float* d, uint32_t a0, uint32_t a1, uint32_t a2,
                                        uint32_t a3, uint32_t b0, uint32_t b1) {
    asm volatile(
        "mma.sync.aligned.m16n8k16.row.col.f32.f16.f16.f32 "
        "{%0,%1,%2,%3}, {%4,%5,%6,%7}, {%8,%9}, {%0,%1,%2,%3};"
        : "+f"(d[0]), "+f"(d[1]), "+f"(d[2]), "+f"(d[3])
        : "r"(a0), "r"(a1), "r"(a2), "r"(a3), "r"(b0), "r"(b1));
}
__device__ __forceinline__ void ldsm_x4(uint32_t& a0, uint32_t& a1, uint32_t& a2, uint32_t& a3,
                                        uint32_t saddr) {
    asm volatile("ldmatrix.sync.aligned.m8n8.x4.shared.b16 {%0,%1,%2,%3}, [%4];"
                 : "=r"(a0), "=r"(a1), "=r"(a2), "=r"(a3) : "r"(saddr));
}
__device__ __forceinline__ uint32_t smem_u32(const void* p) {
    uint32_t a;
    asm("{ .reg .u64 t; cvta.to.shared.u64 t, %1; cvt.u32.u64 %0, t; }" : "=r"(a) : "l"(p));
    return a;
}

// ---------------- fused edge GEMM (mma.sync fp16 2-term, M=64 full-N CTAs) ----------------
// CTA: 256 threads, 64 edges x 256 interleaved cols (2c=f_c, 2c+1=s_c), K=128.
// Warps: warpM = wid&1 (32 rows), warpN = wid>>1 (8 ntiles = 64 interleaved cols).
// smem: [0,256) src, [256,512) tgt,
//       A hi [512, 17920) 64x272B,  A lo [17920, 35328),
//       B table [35328, 100864) = 64 KB (hi term only).
//       D overlay at 512: 64 x 260 fp32 (66560 B; fits in A+B region).
// ~98.5 KB -> 2 CTAs/SM.
#define SM_SRC 0
#define SM_TGT 256
#define SM_AHI 512
#define SM_ALO (512 + 64 * 272)
#define SM_B   (512 + 2 * 64 * 272)
#define SM_D   512
#define DSTRIDE 260
#define EDGE_SMEM (SM_B + 65536)

__global__ __launch_bounds__(256, 2) void edge_fused_mma(
    const float* __restrict__ A,
    const int* __restrict__ src, const int* __restrict__ tgt,
    const float* __restrict__ bf, const float* __restrict__ bs)
{
    extern __shared__ char basep[];
    const uint32_t sbase = smem_u32(basep);
    const int tid = threadIdx.x;
    const int wid = tid >> 5;
    const int lane = tid & 31;
    const int row0 = blockIdx.x * 64;
    const int warpM = wid & 1;         // 32 rows each
    const int warpN = wid >> 1;        // 8 ntiles each

    int* s_src = reinterpret_cast<int*>(basep + SM_SRC);
    int* s_tgt = reinterpret_cast<int*>(basep + SM_TGT);
    if (tid < 64) {
        int r = row0 + tid;
        s_src[tid] = (r < N_EDGES) ? src[r] : 0;
        s_tgt[tid] = (r < N_EDGES) ? tgt[r] : 0;
    }

    // B table: 64 KB = 4096 int4 / 256 threads = 16 each
    {
        int4* dst = reinterpret_cast<int4*>(basep + SM_B);
        const int4* s = reinterpret_cast<const int4*>(g_Bfrag);
#pragma unroll
        for (int i = 0; i < 16; i++) dst[i * 256 + tid] = s[i * 256 + tid];
    }

    // A tile: 64x128 fp32 -> fp16 hi/lo smem (row stride 272 B)
    {
        char* ahi = basep + SM_AHI;
        char* alo = basep + SM_ALO;
#pragma unroll
        for (int it = 0; it < 8; it++) {
            int lin = it * 256 + tid;        // float4 over 64x32
            int row = lin >> 5;
            int c4 = (lin & 31) << 2;
            int e = row0 + row;
            float4 v = make_float4(0.f, 0.f, 0.f, 0.f);
            if (e < N_EDGES) v = *reinterpret_cast<const float4*>(A + (size_t)e * 128 + c4);
            __half h0 = __float2half_rn(v.x), h1 = __float2half_rn(v.y);
            __half h2 = __float2half_rn(v.z), h3 = __float2half_rn(v.w);
            __half l0 = __float2half_rn(v.x - __half2float(h0));
            __half l1 = __float2half_rn(v.y - __half2float(h1));
            __half l2 = __float2half_rn(v.z - __half2float(h2));
            __half l3 = __float2half_rn(v.w - __half2float(h3));
            uint2 hp, lp;
            hp.x = (uint32_t)__half_as_ushort(h0) | ((uint32_t)__half_as_ushort(h1) << 16);
            hp.y = (uint32_t)__half_as_ushort(h2) | ((uint32_t)__half_as_ushort(h3) << 16);
            lp.x = (uint32_t)__half_as_ushort(l0) | ((uint32_t)__half_as_ushort(l1) << 16);
            lp.y = (uint32_t)__half_as_ushort(l2) | ((uint32_t)__half_as_ushort(l3) << 16);
            int off = row * 272 + c4 * 2;
            *reinterpret_cast<uint2*>(ahi + off) = hp;
            *reinterpret_cast<uint2*>(alo + off) = lp;
        }
    }
    __syncthreads();

    float acc[2][8][4];
#pragma unroll
    for (int mt = 0; mt < 2; mt++)
#pragma unroll
        for (int nt = 0; nt < 8; nt++)
#pragma unroll
            for (int j = 0; j < 4; j++) acc[mt][nt][j] = 0.f;

    // mainloop: ldmatrix A frags, smem B frags, 2-term fp16 split (A*Bh with A=ah+al)
    {
        const uint2* bp = reinterpret_cast<const uint2*>(basep + SM_B);
        const uint32_t a_lane_off = (uint32_t)((lane & 15) * 272 + (lane >> 4) * 16);
#pragma unroll
        for (int kstep = 0; kstep < 8; kstep++) {
            uint2 bh[8];
#pragma unroll
            for (int nt = 0; nt < 8; nt++)
                bh[nt] = bp[(kstep * 32 + warpN * 8 + nt) * 32 + lane];
#pragma unroll
            for (int mt = 0; mt < 2; mt++) {
                uint32_t rowbase = (uint32_t)((warpM * 32 + mt * 16) * 272 + kstep * 32);
                uint32_t ah0, ah1, ah2, ah3, al0, al1, al2, al3;
                ldsm_x4(ah0, ah1, ah2, ah3, sbase + SM_AHI + rowbase + a_lane_off);
                ldsm_x4(al0, al1, al2, al3, sbase + SM_ALO + rowbase + a_lane_off);
#pragma unroll
                for (int nt = 0; nt < 8; nt++)
                    mma_f16(acc[mt][nt], ah0, ah1, ah2, ah3, bh[nt].x, bh[nt].y);
#pragma unroll
                for (int nt = 0; nt < 8; nt++)
                    mma_f16(acc[mt][nt], al0, al1, al2, al3, bh[nt].x, bh[nt].y);
            }
        }
    }
    __syncthreads();   // A + B regions dead; reuse as D staging

    // acc -> smem D [64][DSTRIDE]
    {
        float* Dsm = reinterpret_cast<float*>(basep + SM_D);
#pragma unroll
        for (int mt = 0; mt < 2; mt++) {
            int row = warpM * 32 + mt * 16 + (lane >> 2);
#pragma unroll
            for (int nt = 0; nt < 8; nt++) {
                int col = warpN * 64 + nt * 8 + (lane & 3) * 2;
                float* p0 = Dsm + (size_t)row * DSTRIDE + col;
                p0[0] = acc[mt][nt][0];
                p0[1] = acc[mt][nt][1];
                float* p1 = p0 + 8 * DSTRIDE;
                p1[0] = acc[mt][nt][2];
                p1[1] = acc[mt][nt][3];
            }
        }
    }
    __syncthreads();

    // epilogue: gate + scatter (cols interleaved: 2c=f_c, 2c+1=s_c)
    {
        const float* Dsm = reinterpret_cast<const float*>(basep + SM_D);
        const int tr = tid >> 5;   // 8 groups x 8 rows
        const int tc = tid & 31;   // orig cols tc*4..+3
        const float4 bfv = *reinterpret_cast<const float4*>(bf + tc * 4);
        const float4 bsv = *reinterpret_cast<const float4*>(bs + tc * 4);
#pragma unroll 4
        for (int i = 0; i < 8; i++) {
            int lr = tr * 8 + i;
            int e = row0 + lr;
            if (e >= N_EDGES) break;
            int sN = s_src[lr];
            int tN = s_tgt[lr];
            const float* dp = Dsm + (size_t)lr * DSTRIDE + tc * 8;
            float4 d0 = *reinterpret_cast<const float4*>(dp);       // f0,s0,f1,s1
            float4 d1 = *reinterpret_cast<const float4*>(dp + 4);   // f2,s2,f3,s3

            const float4 pf1 = *reinterpret_cast<const float4*>(g_P + (size_t)sN * 512 + 0   + tc * 4);
            const float4 pf2 = *reinterpret_cast<const float4*>(g_P + (size_t)tN * 512 + 128 + tc * 4);
            const float4 ps1 = *reinterpret_cast<const float4*>(g_P + (size_t)sN * 512 + 256 + tc * 4);
            const float4 ps2 = *reinterpret_cast<const float4*>(g_P + (size_t)tN * 512 + 384 + tc * 4);

            float f0 = d0.x + pf1.x + pf2.x + bfv.x;
            float s0 = d0.y + ps1.x + ps2.x + bsv.x;
            float f1 = d0.z + pf1.y + pf2.y + bfv.y;
            float s1 = d0.w + ps1.y + ps2.y + bsv.y;
            float f2 = d1.x + pf1.z + pf2.z + bfv.z;
            float s2 = d1.y + ps1.z + ps2.z + bsv.z;
            float f3 = d1.z + pf1.w + pf2.w + bfv.w;
            float s3 = d1.w + ps1.w + ps2.w + bsv.w;

            float m0 = sigmoidf_(f0) * softplusf_(s0);
            float m1 = sigmoidf_(f1) * softplusf_(s1);
            float m2 = sigmoidf_(f2) * softplusf_(s2);
            float m3 = sigmoidf_(f3) * softplusf_(s3);

            float* dst = g_agg + (size_t)sN * D + tc * 4;
            asm volatile("red.global.add.v4.f32 [%0], {%1, %2, %3, %4};"
                         :: "l"(dst), "f"(m0), "f"(m1), "f"(m2), "f"(m3) : "memory");
        }
    }
}

// ---------------- BN stats ----------------
__global__ __launch_bounds__(128) void bn_stats() {
    const int d = threadIdx.x;
    float sum = 0.f, sq = 0.f;
    for (int n = blockIdx.x; n < N_NODES; n += gridDim.x) {
        float v = g_agg[(size_t)n * D + d];
        sum += v;
        sq += v * v;
    }
    atomicAdd(&g_stats[d], sum);
    atomicAdd(&g_stats[D + d], sq);
}

// ---------------- BN apply + residual + softplus ----------------
__global__ __launch_bounds__(256) void final_kernel(
    const float* __restrict__ x, const float* __restrict__ gamma,
    const float* __restrict__ beta, float* __restrict__ out)
{
    const float invN = 1.0f / (float)N_NODES;
    for (size_t idx = (size_t)blockIdx.x * blockDim.x + threadIdx.x;
         idx < (size_t)N_NODES * D;
         idx += (size_t)gridDim.x * blockDim.x) {
        int d = (int)(idx & (D - 1));
        float mean = g_stats[d] * invN;
        float var = g_stats[D + d] * invN - mean * mean;
        float rstd = rsqrtf(var + BN_EPS);
        float a = (g_agg[idx] - mean) * rstd * gamma[d] + beta[d];
        out[idx] = softplusf_(x[idx] + a);
    }
}

// ---------------- launch ----------------
extern "C" void kernel_launch(void* const* d_in, const int* in_sizes, int n_in,
                              void* d_out, int out_size) {
    const float* x         = (const float*)d_in[0];
    const float* edge_attr = (const float*)d_in[1];
    const int*   edge_src  = (const int*)d_in[2];
    const int*   edge_tgt  = (const int*)d_in[3];
    const float* Wf        = (const float*)d_in[4];
    const float* bf        = (const float*)d_in[5];
    const float* Ws        = (const float*)d_in[6];
    const float* bs        = (const float*)d_in[7];
    const float* gamma     = (const float*)d_in[8];
    const float* beta      = (const float*)d_in[9];
    float* out = (float*)d_out;

    static bool attr_set = false;
    if (!attr_set) {
        cudaFuncSetAttribute(edge_fused_mma, cudaFuncAttributeMaxDynamicSharedMemorySize, EDGE_SMEM);
        attr_set = true;
    }

    prep_weights<<<256, 256>>>(Wf, Ws);
    zero_scratch<<<4096, 256>>>();
    {
        dim3 grid(512 / BN, (N_NODES + BM - 1) / BM);
        node_gemm<<<grid, 256>>>(x, N_NODES);
    }
    {
        int blocks = (N_EDGES + 63) / 64;
        edge_fused_mma<<<blocks, 256, EDGE_SMEM>>>(edge_attr, edge_src, edge_tgt, bf, bs);
    }
    bn_stats<<<512, 128>>>();
    final_kernel<<<(N_NODES * D + 255) / 256, 256>>>(x, gamma, beta, out);
}

// round 10
// speedup vs baseline: 1.5174x; 1.2058x over previous
#include <cuda_runtime.h>
#include <cuda_bf16.h>
#include <cuda_fp16.h>
#include <math.h>
#include <stdint.h>

#define N_NODES 50000
#define N_EDGES 500000
#define D 128
#define BN_EPS 1e-5f

// ---------------- scratch (static device globals; no allocation) ----------------
__device__ float g_P[(size_t)N_NODES * 512];     // [PF1|PF2|PS1|PS2] per node
__device__ float g_agg[(size_t)N_NODES * D];     // scatter-sum target
__device__ float g_stats[2 * D];                 // [sum | sumsq]
// Edge-B fragments for mma.sync m16n8k16 (f16), hi term only, fragment-linear:
// u32 index = (((kstep*32 + ntile)*32) + lane)*2 + reg
// B logical: [k=128][n=256], n=2c -> Wf[256+k][c], n=2c+1 -> Ws[256+k][c]
__device__ __align__(16) uint32_t g_Bfrag[8 * 32 * 32 * 2];      // 64 KB
// Node-B fragments (B1 = concat weights for x@[Wf_a|Wf_b|Ws_a|Ws_b], [k=128][n=512]):
// u32 index = (((kstep*64 + ntile)*32) + lane)*2 + reg
__device__ __align__(16) uint32_t g_B1frag[8 * 64 * 32 * 2];     // 128 KB

// B1 logical value: [k][j], j<128->Wf[k][j]; <256->Wf[128+k][j-128]; <384->Ws[k][j-256]; else Ws[128+k][j-384]
__device__ __forceinline__ float b1_val(const float* Wf, const float* Ws, int k, int j) {
    if (j < 128)      return Wf[k * 128 + j];
    else if (j < 256) return Wf[(128 + k) * 128 + (j - 128)];
    else if (j < 384) return Ws[k * 128 + (j - 256)];
    else              return Ws[(128 + k) * 128 + (j - 384)];
}

// ---------------- weight repack ----------------
__global__ void prep_weights(const float* __restrict__ Wf, const float* __restrict__ Ws) {
    int i = blockIdx.x * blockDim.x + threadIdx.x;
    // edge B frags (16384 u32)
    if (i < 16384) {
        int reg   = i & 1;
        int lane  = (i >> 1) & 31;
        int ntile = (i >> 6) & 31;
        int kstep = (i >> 11) & 7;
        int k0 = kstep * 16 + (lane & 3) * 2 + reg * 8;
        int n  = ntile * 8 + (lane >> 2);
        int c  = n >> 1;
        const float* W = (n & 1) ? Ws : Wf;
        __half h0 = __float2half_rn(W[(256 + k0) * 128 + c]);
        __half h1 = __float2half_rn(W[(256 + k0 + 1) * 128 + c]);
        g_Bfrag[i] = (uint32_t)__half_as_ushort(h0) | ((uint32_t)__half_as_ushort(h1) << 16);
    }
    // node B frags (32768 u32)
    if (i < 32768) {
        int reg   = i & 1;
        int lane  = (i >> 1) & 31;
        int ntile = (i >> 6) & 63;
        int kstep = (i >> 12) & 7;
        int k0 = kstep * 16 + (lane & 3) * 2 + reg * 8;
        int n  = ntile * 8 + (lane >> 2);
        __half h0 = __float2half_rn(b1_val(Wf, Ws, k0, n));
        __half h1 = __float2half_rn(b1_val(Wf, Ws, k0 + 1, n));
        g_B1frag[i] = (uint32_t)__half_as_ushort(h0) | ((uint32_t)__half_as_ushort(h1) << 16);
    }
}

// ---------------- zero scratch ----------------
__global__ void zero_scratch() {
    size_t n4 = (size_t)N_NODES * D / 4;
    float4* p = reinterpret_cast<float4*>(g_agg);
    for (size_t i = blockIdx.x * blockDim.x + threadIdx.x; i < n4; i += (size_t)gridDim.x * blockDim.x)
        p[i] = make_float4(0.f, 0.f, 0.f, 0.f);
    int t = blockIdx.x * blockDim.x + threadIdx.x;
    if (t < 2 * D) g_stats[t] = 0.f;
}

// ---------------- shared mma helpers ----------------
__device__ __forceinline__ float sigmoidf_(float x) { return 1.f / (1.f + expf(-x)); }
__device__ __forceinline__ float softplusf_(float x) {
    return fmaxf(x, 0.f) + log1pf(expf(-fabsf(x)));
}
__device__ __forceinline__ void mma_f16(float* d, uint32_t a0, uint32_t a1, uint32_t a2,
                                        uint32_t a3, uint32_t b0, uint32_t b1) {
    asm volatile(
        "mma.sync.aligned.m16n8k16.row.col.f32.f16.f16.f32 "
        "{%0,%1,%2,%3}, {%4,%5,%6,%7}, {%8,%9}, {%0,%1,%2,%3};"
        : "+f"(d[0]), "+f"(d[1]), "+f"(d[2]), "+f"(d[3])
        : "r"(a0), "r"(a1), "r"(a2), "r"(a3), "r"(b0), "r"(b1));
}
__device__ __forceinline__ void ldsm_x4(uint32_t& a0, uint32_t& a1, uint32_t& a2, uint32_t& a3,
                                        uint32_t saddr) {
    asm volatile("ldmatrix.sync.aligned.m8n8.x4.shared.b16 {%0,%1,%2,%3}, [%4];"
                 : "=r"(a0), "=r"(a1), "=r"(a2), "=r"(a3) : "r"(saddr));
}
__device__ __forceinline__ uint32_t smem_u32(const void* p) {
    uint32_t a;
    asm("{ .reg .u64 t; cvta.to.shared.u64 t, %1; cvt.u32.u64 %0, t; }" : "=r"(a) : "l"(p));
    return a;
}

// A-tile loader: rows0..rows0+63 of src[M,128] fp32 -> fp16 hi/lo smem (272B stride)
__device__ __forceinline__ void load_a_split(const float* __restrict__ A, int row0, int M,
                                             char* ahi, char* alo, int tid) {
#pragma unroll
    for (int it = 0; it < 8; it++) {
        int lin = it * 256 + tid;        // float4 over 64x32
        int row = lin >> 5;
        int c4 = (lin & 31) << 2;
        int e = row0 + row;
        float4 v = make_float4(0.f, 0.f, 0.f, 0.f);
        if (e < M) v = *reinterpret_cast<const float4*>(A + (size_t)e * 128 + c4);
        __half h0 = __float2half_rn(v.x), h1 = __float2half_rn(v.y);
        __half h2 = __float2half_rn(v.z), h3 = __float2half_rn(v.w);
        __half l0 = __float2half_rn(v.x - __half2float(h0));
        __half l1 = __float2half_rn(v.y - __half2float(h1));
        __half l2 = __float2half_rn(v.z - __half2float(h2));
        __half l3 = __float2half_rn(v.w - __half2float(h3));
        uint2 hp, lp;
        hp.x = (uint32_t)__half_as_ushort(h0) | ((uint32_t)__half_as_ushort(h1) << 16);
        hp.y = (uint32_t)__half_as_ushort(h2) | ((uint32_t)__half_as_ushort(h3) << 16);
        lp.x = (uint32_t)__half_as_ushort(l0) | ((uint32_t)__half_as_ushort(l1) << 16);
        lp.y = (uint32_t)__half_as_ushort(l2) | ((uint32_t)__half_as_ushort(l3) << 16);
        int off = row * 272 + c4 * 2;
        *reinterpret_cast<uint2*>(ahi + off) = hp;
        *reinterpret_cast<uint2*>(alo + off) = lp;
    }
}

// ---------------- node GEMM (mma.sync fp16 2-term): g_P[M,512] = x @ B1 ----------------
// CTA: 256 thr, 64 rows x 256 cols (col half h = blockIdx.y).
// smem: A hi [0,17408), A lo [17408,34816), B slice [34816,100352) = 64 KB.
#define NSM_AHI 0
#define NSM_ALO (64 * 272)
#define NSM_B   (2 * 64 * 272)
#define NODE_SMEM (NSM_B + 65536)

__global__ __launch_bounds__(256, 2) void node_gemm_mma(const float* __restrict__ X)
{
    extern __shared__ char basep[];
    const uint32_t sbase = smem_u32(basep);
    const int tid = threadIdx.x;
    const int wid = tid >> 5;
    const int lane = tid & 31;
    const int row0 = blockIdx.x * 64;
    const int h = blockIdx.y;          // col half: cols [h*256, h*256+256)
    const int warpM = wid & 1;
    const int warpN = wid >> 1;

    // B slice: 4096 int4; global per-kstep 1024 int4, take half h (512)
    {
        int4* dst = reinterpret_cast<int4*>(basep + NSM_B);
        const int4* s = reinterpret_cast<const int4*>(g_B1frag);
#pragma unroll
        for (int it = 0; it < 16; it++) {
            int idx = it * 256 + tid;
            int kstep = idx >> 9;
            int within = idx & 511;
            dst[idx] = s[kstep * 1024 + h * 512 + within];
        }
    }
    load_a_split(X, row0, N_NODES, basep + NSM_AHI, basep + NSM_ALO, tid);
    __syncthreads();

    float acc[2][8][4];
#pragma unroll
    for (int mt = 0; mt < 2; mt++)
#pragma unroll
        for (int nt = 0; nt < 8; nt++)
#pragma unroll
            for (int j = 0; j < 4; j++) acc[mt][nt][j] = 0.f;

    {
        const uint2* bp = reinterpret_cast<const uint2*>(basep + NSM_B);
        const uint32_t a_lane_off = (uint32_t)((lane & 15) * 272 + (lane >> 4) * 16);
#pragma unroll
        for (int kstep = 0; kstep < 8; kstep++) {
            uint2 bh[8];
#pragma unroll
            for (int nt = 0; nt < 8; nt++)
                bh[nt] = bp[(kstep * 32 + warpN * 8 + nt) * 32 + lane];
#pragma unroll
            for (int mt = 0; mt < 2; mt++) {
                uint32_t rowbase = (uint32_t)((warpM * 32 + mt * 16) * 272 + kstep * 32);
                uint32_t ah0, ah1, ah2, ah3, al0, al1, al2, al3;
                ldsm_x4(ah0, ah1, ah2, ah3, sbase + NSM_AHI + rowbase + a_lane_off);
                ldsm_x4(al0, al1, al2, al3, sbase + NSM_ALO + rowbase + a_lane_off);
#pragma unroll
                for (int nt = 0; nt < 8; nt++)
                    mma_f16(acc[mt][nt], ah0, ah1, ah2, ah3, bh[nt].x, bh[nt].y);
#pragma unroll
                for (int nt = 0; nt < 8; nt++)
                    mma_f16(acc[mt][nt], al0, al1, al2, al3, bh[nt].x, bh[nt].y);
            }
        }
    }

    // direct store: acc pairs are column-adjacent
#pragma unroll
    for (int mt = 0; mt < 2; mt++) {
        int rowl = warpM * 32 + mt * 16 + (lane >> 2);
#pragma unroll
        for (int nt = 0; nt < 8; nt++) {
            int col = h * 256 + warpN * 64 + nt * 8 + (lane & 3) * 2;
            int r0 = row0 + rowl;
            if (r0 < N_NODES) {
                float2 v = make_float2(acc[mt][nt][0], acc[mt][nt][1]);
                *reinterpret_cast<float2*>(g_P + (size_t)r0 * 512 + col) = v;
            }
            int r1 = r0 + 8;
            if (r1 < N_NODES) {
                float2 v = make_float2(acc[mt][nt][2], acc[mt][nt][3]);
                *reinterpret_cast<float2*>(g_P + (size_t)r1 * 512 + col) = v;
            }
        }
    }
}

// ---------------- fused edge GEMM (mma.sync fp16 2-term, M=64 full-N CTAs) ----------------
#define SM_SRC 0
#define SM_TGT 256
#define SM_AHI 512
#define SM_ALO (512 + 64 * 272)
#define SM_B   (512 + 2 * 64 * 272)
#define SM_D   512
#define DSTRIDE 260
#define EDGE_SMEM (SM_B + 65536)

__global__ __launch_bounds__(256, 2) void edge_fused_mma(
    const float* __restrict__ A,
    const int* __restrict__ src, const int* __restrict__ tgt,
    const float* __restrict__ bf, const float* __restrict__ bs)
{
    extern __shared__ char basep[];
    const uint32_t sbase = smem_u32(basep);
    const int tid = threadIdx.x;
    const int wid = tid >> 5;
    const int lane = tid & 31;
    const int row0 = blockIdx.x * 64;
    const int warpM = wid & 1;
    const int warpN = wid >> 1;

    int* s_src = reinterpret_cast<int*>(basep + SM_SRC);
    int* s_tgt = reinterpret_cast<int*>(basep + SM_TGT);
    if (tid < 64) {
        int r = row0 + tid;
        s_src[tid] = (r < N_EDGES) ? src[r] : 0;
        s_tgt[tid] = (r < N_EDGES) ? tgt[r] : 0;
    }

    {
        int4* dst = reinterpret_cast<int4*>(basep + SM_B);
        const int4* s = reinterpret_cast<const int4*>(g_Bfrag);
#pragma unroll
        for (int i = 0; i < 16; i++) dst[i * 256 + tid] = s[i * 256 + tid];
    }
    load_a_split(A, row0, N_EDGES, basep + SM_AHI, basep + SM_ALO, tid);
    __syncthreads();

    float acc[2][8][4];
#pragma unroll
    for (int mt = 0; mt < 2; mt++)
#pragma unroll
        for (int nt = 0; nt < 8; nt++)
#pragma unroll
            for (int j = 0; j < 4; j++) acc[mt][nt][j] = 0.f;

    {
        const uint2* bp = reinterpret_cast<const uint2*>(basep + SM_B);
        const uint32_t a_lane_off = (uint32_t)((lane & 15) * 272 + (lane >> 4) * 16);
#pragma unroll
        for (int kstep = 0; kstep < 8; kstep++) {
            uint2 bh[8];
#pragma unroll
            for (int nt = 0; nt < 8; nt++)
                bh[nt] = bp[(kstep * 32 + warpN * 8 + nt) * 32 + lane];
#pragma unroll
            for (int mt = 0; mt < 2; mt++) {
                uint32_t rowbase = (uint32_t)((warpM * 32 + mt * 16) * 272 + kstep * 32);
                uint32_t ah0, ah1, ah2, ah3, al0, al1, al2, al3;
                ldsm_x4(ah0, ah1, ah2, ah3, sbase + SM_AHI + rowbase + a_lane_off);
                ldsm_x4(al0, al1, al2, al3, sbase + SM_ALO + rowbase + a_lane_off);
#pragma unroll
                for (int nt = 0; nt < 8; nt++)
                    mma_f16(acc[mt][nt], ah0, ah1, ah2, ah3, bh[nt].x, bh[nt].y);
#pragma unroll
                for (int nt = 0; nt < 8; nt++)
                    mma_f16(acc[mt][nt], al0, al1, al2, al3, bh[nt].x, bh[nt].y);
            }
        }
    }
    __syncthreads();   // A + B regions dead; reuse as D staging

    {
        float* Dsm = reinterpret_cast<float*>(basep + SM_D);
#pragma unroll
        for (int mt = 0; mt < 2; mt++) {
            int row = warpM * 32 + mt * 16 + (lane >> 2);
#pragma unroll
            for (int nt = 0; nt < 8; nt++) {
                int col = warpN * 64 + nt * 8 + (lane & 3) * 2;
                float* p0 = Dsm + (size_t)row * DSTRIDE + col;
                p0[0] = acc[mt][nt][0];
                p0[1] = acc[mt][nt][1];
                float* p1 = p0 + 8 * DSTRIDE;
                p1[0] = acc[mt][nt][2];
                p1[1] = acc[mt][nt][3];
            }
        }
    }
    __syncthreads();

    {
        const float* Dsm = reinterpret_cast<const float*>(basep + SM_D);
        const int tr = tid >> 5;
        const int tc = tid & 31;
        const float4 bfv = *reinterpret_cast<const float4*>(bf + tc * 4);
        const float4 bsv = *reinterpret_cast<const float4*>(bs + tc * 4);
#pragma unroll 4
        for (int i = 0; i < 8; i++) {
            int lr = tr * 8 + i;
            int e = row0 + lr;
            if (e >= N_EDGES) break;
            int sN = s_src[lr];
            int tN = s_tgt[lr];
            const float* dp = Dsm + (size_t)lr * DSTRIDE + tc * 8;
            float4 d0 = *reinterpret_cast<const float4*>(dp);
            float4 d1 = *reinterpret_cast<const float4*>(dp + 4);

            const float4 pf1 = *reinterpret_cast<const float4*>(g_P + (size_t)sN * 512 + 0   + tc * 4);
            const float4 pf2 = *reinterpret_cast<const float4*>(g_P + (size_t)tN * 512 + 128 + tc * 4);
            const float4 ps1 = *reinterpret_cast<const float4*>(g_P + (size_t)sN * 512 + 256 + tc * 4);
            const float4 ps2 = *reinterpret_cast<const float4*>(g_P + (size_t)tN * 512 + 384 + tc * 4);

            float f0 = d0.x + pf1.x + pf2.x + bfv.x;
            float s0 = d0.y + ps1.x + ps2.x + bsv.x;
            float f1 = d0.z + pf1.y + pf2.y + bfv.y;
            float s1 = d0.w + ps1.y + ps2.y + bsv.y;
            float f2 = d1.x + pf1.z + pf2.z + bfv.z;
            float s2 = d1.y + ps1.z + ps2.z + bsv.z;
            float f3 = d1.z + pf1.w + pf2.w + bfv.w;
            float s3 = d1.w + ps1.w + ps2.w + bsv.w;

            float m0 = sigmoidf_(f0) * softplusf_(s0);
            float m1 = sigmoidf_(f1) * softplusf_(s1);
            float m2 = sigmoidf_(f2) * softplusf_(s2);
            float m3 = sigmoidf_(f3) * softplusf_(s3);

            float* dst = g_agg + (size_t)sN * D + tc * 4;
            asm volatile("red.global.add.v4.f32 [%0], {%1, %2, %3, %4};"
                         :: "l"(dst), "f"(m0), "f"(m1), "f"(m2), "f"(m3) : "memory");
        }
    }
}

// ---------------- BN stats ----------------
__global__ __launch_bounds__(128) void bn_stats() {
    const int d = threadIdx.x;
    float sum = 0.f, sq = 0.f;
    for (int n = blockIdx.x; n < N_NODES; n += gridDim.x) {
        float v = g_agg[(size_t)n * D + d];
        sum += v;
        sq += v * v;
    }
    atomicAdd(&g_stats[d], sum);
    atomicAdd(&g_stats[D + d], sq);
}

// ---------------- BN apply + residual + softplus ----------------
__global__ __launch_bounds__(256) void final_kernel(
    const float* __restrict__ x, const float* __restrict__ gamma,
    const float* __restrict__ beta, float* __restrict__ out)
{
    const float invN = 1.0f / (float)N_NODES;
    for (size_t idx = (size_t)blockIdx.x * blockDim.x + threadIdx.x;
         idx < (size_t)N_NODES * D;
         idx += (size_t)gridDim.x * blockDim.x) {
        int d = (int)(idx & (D - 1));
        float mean = g_stats[d] * invN;
        float var = g_stats[D + d] * invN - mean * mean;
        float rstd = rsqrtf(var + BN_EPS);
        float a = (g_agg[idx] - mean) * rstd * gamma[d] + beta[d];
        out[idx] = softplusf_(x[idx] + a);
    }
}

// ---------------- launch ----------------
extern "C" void kernel_launch(void* const* d_in, const int* in_sizes, int n_in,
                              void* d_out, int out_size) {
    const float* x         = (const float*)d_in[0];
    const float* edge_attr = (const float*)d_in[1];
    const int*   edge_src  = (const int*)d_in[2];
    const int*   edge_tgt  = (const int*)d_in[3];
    const float* Wf        = (const float*)d_in[4];
    const float* bf        = (const float*)d_in[5];
    const float* Ws        = (const float*)d_in[6];
    const float* bs        = (const float*)d_in[7];
    const float* gamma     = (const float*)d_in[8];
    const float* beta      = (const float*)d_in[9];
    float* out = (float*)d_out;

    static bool attr_set = false;
    if (!attr_set) {
        cudaFuncSetAttribute(edge_fused_mma, cudaFuncAttributeMaxDynamicSharedMemorySize, EDGE_SMEM);
        cudaFuncSetAttribute(node_gemm_mma, cudaFuncAttributeMaxDynamicSharedMemorySize, NODE_SMEM);
        attr_set = true;
    }

    prep_weights<<<128, 256>>>(Wf, Ws);
    zero_scratch<<<4096, 256>>>();
    {
        dim3 grid((N_NODES + 63) / 64, 2);
        node_gemm_mma<<<grid, 256, NODE_SMEM>>>(x);
    }
    {
        int blocks = (N_EDGES + 63) / 64;
        edge_fused_mma<<<blocks, 256, EDGE_SMEM>>>(edge_attr, edge_src, edge_tgt, bf, bs);
    }
    bn_stats<<<512, 128>>>();
    final_kernel<<<(N_NODES * D + 255) / 256, 256>>>(x, gamma, beta, out);
}

// round 12
// speedup vs baseline: 1.5451x; 1.0183x over previous
#include <cuda_runtime.h>
#include <cuda_bf16.h>
#include <cuda_fp16.h>
#include <math.h>
#include <stdint.h>

#define N_NODES 50000
#define N_EDGES 500000
#define D 128
#define BN_EPS 1e-5f

#define NT_EDGE ((N_EDGES + 63) / 64)   // 7813
#define NT_NODE ((N_NODES + 63) / 64)   // 782

// ---------------- scratch (static device globals; no allocation) ----------------
__device__ float g_P[(size_t)N_NODES * 512];     // [PF1|PF2|PS1|PS2] per node
__device__ float g_agg[(size_t)N_NODES * D];     // scatter-sum target
__device__ float g_stats[2 * D];                 // [sum | sumsq]
// Edge-B fragments for mma.sync m16n8k16 (f16), hi term, fragment-linear:
// u32 index = (((kstep*32 + ntile)*32) + lane)*2 + reg
__device__ __align__(16) uint32_t g_Bfrag[8 * 32 * 32 * 2];      // 64 KB
// Node-B fragments ([k=128][n=512]): u32 index = (((kstep*64 + ntile)*32) + lane)*2 + reg
__device__ __align__(16) uint32_t g_B1frag[8 * 64 * 32 * 2];     // 128 KB

__device__ __forceinline__ float b1_val(const float* Wf, const float* Ws, int k, int j) {
    if (j < 128)      return Wf[k * 128 + j];
    else if (j < 256) return Wf[(128 + k) * 128 + (j - 128)];
    else if (j < 384) return Ws[k * 128 + (j - 256)];
    else              return Ws[(128 + k) * 128 + (j - 384)];
}

// ---------------- weight repack ----------------
__global__ void prep_weights(const float* __restrict__ Wf, const float* __restrict__ Ws) {
    int i = blockIdx.x * blockDim.x + threadIdx.x;
    if (i < 16384) {
        int reg   = i & 1;
        int lane  = (i >> 1) & 31;
        int ntile = (i >> 6) & 31;
        int kstep = (i >> 11) & 7;
        int k0 = kstep * 16 + (lane & 3) * 2 + reg * 8;
        int n  = ntile * 8 + (lane >> 2);
        int c  = n >> 1;
        const float* W = (n & 1) ? Ws : Wf;
        __half h0 = __float2half_rn(W[(256 + k0) * 128 + c]);
        __half h1 = __float2half_rn(W[(256 + k0 + 1) * 128 + c]);
        g_Bfrag[i] = (uint32_t)__half_as_ushort(h0) | ((uint32_t)__half_as_ushort(h1) << 16);
    }
    if (i < 32768) {
        int reg   = i & 1;
        int lane  = (i >> 1) & 31;
        int ntile = (i >> 6) & 63;
        int kstep = (i >> 12) & 7;
        int k0 = kstep * 16 + (lane & 3) * 2 + reg * 8;
        int n  = ntile * 8 + (lane >> 2);
        __half h0 = __float2half_rn(b1_val(Wf, Ws, k0, n));
        __half h1 = __float2half_rn(b1_val(Wf, Ws, k0 + 1, n));
        g_B1frag[i] = (uint32_t)__half_as_ushort(h0) | ((uint32_t)__half_as_ushort(h1) << 16);
    }
}

// ---------------- zero scratch ----------------
__global__ void zero_scratch() {
    size_t n4 = (size_t)N_NODES * D / 4;
    float4* p = reinterpret_cast<float4*>(g_agg);
    for (size_t i = blockIdx.x * blockDim.x + threadIdx.x; i < n4; i += (size_t)gridDim.x * blockDim.x)
        p[i] = make_float4(0.f, 0.f, 0.f, 0.f);
    int t = blockIdx.x * blockDim.x + threadIdx.x;
    if (t < 2 * D) g_stats[t] = 0.f;
}

// ---------------- helpers ----------------
__device__ __forceinline__ float sigmoidf_(float x) { return 1.f / (1.f + expf(-x)); }
__device__ __forceinline__ float softplusf_(float x) {
    return fmaxf(x, 0.f) + log1pf(expf(-fabsf(x)));
}
__device__ __forceinline__ void mma_f16(float* d, uint32_t a0, uint32_t a1, uint32_t a2,
                                        uint32_t a3, uint32_t b0, uint32_t b1) {
    asm volatile(
        "mma.sync.aligned.m16n8k16.row.col.f32.f16.f16.f32 "
        "{%0,%1,%2,%3}, {%4,%5,%6,%7}, {%8,%9}, {%0,%1,%2,%3};"
        : "+f"(d[0]), "+f"(d[1]), "+f"(d[2]), "+f"(d[3])
        : "r"(a0), "r"(a1), "r"(a2), "r"(a3), "r"(b0), "r"(b1));
}
__device__ __forceinline__ void ldsm_x4(uint32_t& a0, uint32_t& a1, uint32_t& a2, uint32_t& a3,
                                        uint32_t saddr) {
    asm volatile("ldmatrix.sync.aligned.m8n8.x4.shared.b16 {%0,%1,%2,%3}, [%4];"
                 : "=r"(a0), "=r"(a1), "=r"(a2), "=r"(a3) : "r"(saddr));
}
__device__ __forceinline__ uint32_t smem_u32(const void* p) {
    uint32_t a;
    asm("{ .reg .u64 t; cvta.to.shared.u64 t, %1; cvt.u32.u64 %0, t; }" : "=r"(a) : "l"(p));
    return a;
}

// Load a 64x128 fp32 tile into registers (8 float4/thread); zero padding beyond M.
__device__ __forceinline__ void load_a_regs(const float* __restrict__ A, int row0, int M,
                                            int tid, float4* av) {
#pragma unroll
    for (int it = 0; it < 8; it++) {
        int lin = it * 256 + tid;
        int row = lin >> 5;
        int c4 = (lin & 31) << 2;
        int e = row0 + row;
        av[it] = make_float4(0.f, 0.f, 0.f, 0.f);
        if (e < M) av[it] = *reinterpret_cast<const float4*>(A + (size_t)e * 128 + c4);
    }
}
// Convert+split registers into hi/lo fp16 smem tiles (272B row stride).
__device__ __forceinline__ void store_a_split(const float4* av, char* ahi, char* alo, int tid) {
#pragma unroll
    for (int it = 0; it < 8; it++) {
        int lin = it * 256 + tid;
        int row = lin >> 5;
        int c4 = (lin & 31) << 2;
        float4 v = av[it];
        __half h0 = __float2half_rn(v.x), h1 = __float2half_rn(v.y);
        __half h2 = __float2half_rn(v.z), h3 = __float2half_rn(v.w);
        __half l0 = __float2half_rn(v.x - __half2float(h0));
        __half l1 = __float2half_rn(v.y - __half2float(h1));
        __half l2 = __float2half_rn(v.z - __half2float(h2));
        __half l3 = __float2half_rn(v.w - __half2float(h3));
        uint2 hp, lp;
        hp.x = (uint32_t)__half_as_ushort(h0) | ((uint32_t)__half_as_ushort(h1) << 16);
        hp.y = (uint32_t)__half_as_ushort(h2) | ((uint32_t)__half_as_ushort(h3) << 16);
        lp.x = (uint32_t)__half_as_ushort(l0) | ((uint32_t)__half_as_ushort(l1) << 16);
        lp.y = (uint32_t)__half_as_ushort(l2) | ((uint32_t)__half_as_ushort(l3) << 16);
        int off = row * 272 + c4 * 2;
        *reinterpret_cast<uint2*>(ahi + off) = hp;
        *reinterpret_cast<uint2*>(alo + off) = lp;
    }
}

// ---------------- persistent node GEMM: g_P[M,512] = x @ B1 ----------------
// grid (148, 2); CTA loops tiles of 64 rows; col half h = blockIdx.y.
#define NSM_AHI 0
#define NSM_ALO (64 * 272)
#define NSM_B   (2 * 64 * 272)
#define NODE_SMEM (NSM_B + 65536)

__global__ __launch_bounds__(256, 2) void node_gemm_mma(const float* __restrict__ X)
{
    extern __shared__ char basep[];
    const uint32_t sbase = smem_u32(basep);
    const int tid = threadIdx.x;
    const int wid = tid >> 5;
    const int lane = tid & 31;
    const int h = blockIdx.y;
    const int warpM = wid & 1;
    const int warpN = wid >> 1;

    // B slice once
    {
        int4* dst = reinterpret_cast<int4*>(basep + NSM_B);
        const int4* s = reinterpret_cast<const int4*>(g_B1frag);
#pragma unroll
        for (int it = 0; it < 16; it++) {
            int idx = it * 256 + tid;
            int kstep = idx >> 9;
            int within = idx & 511;
            dst[idx] = s[kstep * 1024 + h * 512 + within];
        }
    }

    int tile = blockIdx.x;
    float4 av[8];
    if (tile < NT_NODE) load_a_regs(X, tile * 64, N_NODES, tid, av);

    while (tile < NT_NODE) {
        store_a_split(av, basep + NSM_AHI, basep + NSM_ALO, tid);
        __syncthreads();

        float acc[2][8][4];
#pragma unroll
        for (int mt = 0; mt < 2; mt++)
#pragma unroll
            for (int nt = 0; nt < 8; nt++)
#pragma unroll
                for (int j = 0; j < 4; j++) acc[mt][nt][j] = 0.f;

        {
            const uint2* bp = reinterpret_cast<const uint2*>(basep + NSM_B);
            const uint32_t a_lane_off = (uint32_t)((lane & 15) * 272 + (lane >> 4) * 16);
#pragma unroll
            for (int kstep = 0; kstep < 8; kstep++) {
                uint2 bh[8];
#pragma unroll
                for (int nt = 0; nt < 8; nt++)
                    bh[nt] = bp[(kstep * 32 + warpN * 8 + nt) * 32 + lane];
#pragma unroll
                for (int mt = 0; mt < 2; mt++) {
                    uint32_t rowbase = (uint32_t)((warpM * 32 + mt * 16) * 272 + kstep * 32);
                    uint32_t ah0, ah1, ah2, ah3, al0, al1, al2, al3;
                    ldsm_x4(ah0, ah1, ah2, ah3, sbase + NSM_AHI + rowbase + a_lane_off);
                    ldsm_x4(al0, al1, al2, al3, sbase + NSM_ALO + rowbase + a_lane_off);
#pragma unroll
                    for (int nt = 0; nt < 8; nt++)
                        mma_f16(acc[mt][nt], ah0, ah1, ah2, ah3, bh[nt].x, bh[nt].y);
#pragma unroll
                    for (int nt = 0; nt < 8; nt++)
                        mma_f16(acc[mt][nt], al0, al1, al2, al3, bh[nt].x, bh[nt].y);
                }
            }
        }

        int row0 = tile * 64;
        int next = tile + gridDim.x;
        if (next < NT_NODE) load_a_regs(X, next * 64, N_NODES, tid, av);

        // direct store epilogue (no smem staging — no overlay hazard)
#pragma unroll
        for (int mt = 0; mt < 2; mt++) {
            int rowl = warpM * 32 + mt * 16 + (lane >> 2);
#pragma unroll
            for (int nt = 0; nt < 8; nt++) {
                int col = h * 256 + warpN * 64 + nt * 8 + (lane & 3) * 2;
                int r0 = row0 + rowl;
                if (r0 < N_NODES) {
                    float2 v = make_float2(acc[mt][nt][0], acc[mt][nt][1]);
                    *reinterpret_cast<float2*>(g_P + (size_t)r0 * 512 + col) = v;
                }
                int r1 = r0 + 8;
                if (r1 < N_NODES) {
                    float2 v = make_float2(acc[mt][nt][2], acc[mt][nt][3]);
                    *reinterpret_cast<float2*>(g_P + (size_t)r1 * 512 + col) = v;
                }
            }
        }
        __syncthreads();   // A smem consumed by all warps before overwrite
        tile = next;
    }
}

// ---------------- persistent fused edge GEMM + gate + scatter ----------------
// D staged in TWO phases of 32 rows each so the overlay stays inside the A
// region (32*260*4 = 33280 <= 34816) and never clobbers the B table (R11 bug).
#define SM_SRC 0
#define SM_TGT 256
#define SM_AHI 512
#define SM_ALO (512 + 64 * 272)
#define SM_B   (512 + 2 * 64 * 272)
#define SM_D   512
#define DSTRIDE 260
#define EDGE_SMEM (SM_B + 65536)

__global__ __launch_bounds__(256, 2) void edge_fused_mma(
    const float* __restrict__ A,
    const int* __restrict__ src, const int* __restrict__ tgt,
    const float* __restrict__ bf, const float* __restrict__ bs)
{
    extern __shared__ char basep[];
    const uint32_t sbase = smem_u32(basep);
    const int tid = threadIdx.x;
    const int wid = tid >> 5;
    const int lane = tid & 31;
    const int warpM = wid & 1;
    const int warpN = wid >> 1;

    int* s_src = reinterpret_cast<int*>(basep + SM_SRC);
    int* s_tgt = reinterpret_cast<int*>(basep + SM_TGT);

    // B table once per CTA
    {
        int4* dst = reinterpret_cast<int4*>(basep + SM_B);
        const int4* s = reinterpret_cast<const int4*>(g_Bfrag);
#pragma unroll
        for (int i = 0; i < 16; i++) dst[i * 256 + tid] = s[i * 256 + tid];
    }

    // epilogue constants
    const int e_tr = tid >> 5;
    const int e_tc = tid & 31;
    const float4 bfv = *reinterpret_cast<const float4*>(bf + e_tc * 4);
    const float4 bsv = *reinterpret_cast<const float4*>(bs + e_tc * 4);

    int tile = blockIdx.x;
    float4 av[8];
    int my_src = 0, my_tgt = 0;
    if (tile < NT_EDGE) {
        load_a_regs(A, tile * 64, N_EDGES, tid, av);
        if (tid < 64) {
            int r = tile * 64 + tid;
            my_src = (r < N_EDGES) ? src[r] : 0;
            my_tgt = (r < N_EDGES) ? tgt[r] : 0;
        }
    }

    while (tile < NT_EDGE) {
        store_a_split(av, basep + SM_AHI, basep + SM_ALO, tid);
        if (tid < 64) { s_src[tid] = my_src; s_tgt[tid] = my_tgt; }
        __syncthreads();

        float acc[2][8][4];
#pragma unroll
        for (int mt = 0; mt < 2; mt++)
#pragma unroll
            for (int nt = 0; nt < 8; nt++)
#pragma unroll
                for (int j = 0; j < 4; j++) acc[mt][nt][j] = 0.f;

        {
            const uint2* bp = reinterpret_cast<const uint2*>(basep + SM_B);
            const uint32_t a_lane_off = (uint32_t)((lane & 15) * 272 + (lane >> 4) * 16);
#pragma unroll
            for (int kstep = 0; kstep < 8; kstep++) {
                uint2 bh[8];
#pragma unroll
                for (int nt = 0; nt < 8; nt++)
                    bh[nt] = bp[(kstep * 32 + warpN * 8 + nt) * 32 + lane];
#pragma unroll
                for (int mt = 0; mt < 2; mt++) {
                    uint32_t rowbase = (uint32_t)((warpM * 32 + mt * 16) * 272 + kstep * 32);
                    uint32_t ah0, ah1, ah2, ah3, al0, al1, al2, al3;
                    ldsm_x4(ah0, ah1, ah2, ah3, sbase + SM_AHI + rowbase + a_lane_off);
                    ldsm_x4(al0, al1, al2, al3, sbase + SM_ALO + rowbase + a_lane_off);
#pragma unroll
                    for (int nt = 0; nt < 8; nt++)
                        mma_f16(acc[mt][nt], ah0, ah1, ah2, ah3, bh[nt].x, bh[nt].y);
#pragma unroll
                    for (int nt = 0; nt < 8; nt++)
                        mma_f16(acc[mt][nt], al0, al1, al2, al3, bh[nt].x, bh[nt].y);
                }
            }
        }
        __syncthreads();   // mainloop done; A region dead (acc live in regs)

        const int row0 = tile * 64;
        const int next = tile + gridDim.x;
        float* Dsm = reinterpret_cast<float*>(basep + SM_D);

#pragma unroll
        for (int phase = 0; phase < 2; phase++) {
            // stage rows [phase*32, phase*32+32): owned by warps with warpM==phase
            if (warpM == phase) {
#pragma unroll
                for (int mt = 0; mt < 2; mt++) {
                    int rowl = mt * 16 + (lane >> 2);   // local 0..31
#pragma unroll
                    for (int nt = 0; nt < 8; nt++) {
                        int col = warpN * 64 + nt * 8 + (lane & 3) * 2;
                        float* p0 = Dsm + (size_t)rowl * DSTRIDE + col;
                        p0[0] = acc[mt][nt][0];
                        p0[1] = acc[mt][nt][1];
                        float* p1 = p0 + 8 * DSTRIDE;
                        p1[0] = acc[mt][nt][2];
                        p1[1] = acc[mt][nt][3];
                    }
                }
            }
            __syncthreads();

            // prefetch next tile once accs are fully dead (after phase-1 staging)
            if (phase == 1 && next < NT_EDGE) {
                load_a_regs(A, next * 64, N_EDGES, tid, av);
                if (tid < 64) {
                    int r = next * 64 + tid;
                    my_src = (r < N_EDGES) ? src[r] : 0;
                    my_tgt = (r < N_EDGES) ? tgt[r] : 0;
                }
            }

            // epilogue for this phase's 32 rows: gate + scatter
#pragma unroll
            for (int i = 0; i < 4; i++) {
                int lr = e_tr * 4 + i;          // local 0..31
                int grow = phase * 32 + lr;     // row within tile
                int e = row0 + grow;
                if (e >= N_EDGES) break;
                int sN = s_src[grow];
                int tN = s_tgt[grow];
                const float* dp = Dsm + (size_t)lr * DSTRIDE + e_tc * 8;
                float4 d0 = *reinterpret_cast<const float4*>(dp);       // f0,s0,f1,s1
                float4 d1 = *reinterpret_cast<const float4*>(dp + 4);   // f2,s2,f3,s3

                const float4 pf1 = *reinterpret_cast<const float4*>(g_P + (size_t)sN * 512 + 0   + e_tc * 4);
                const float4 pf2 = *reinterpret_cast<const float4*>(g_P + (size_t)tN * 512 + 128 + e_tc * 4);
                const float4 ps1 = *reinterpret_cast<const float4*>(g_P + (size_t)sN * 512 + 256 + e_tc * 4);
                const float4 ps2 = *reinterpret_cast<const float4*>(g_P + (size_t)tN * 512 + 384 + e_tc * 4);

                float f0 = d0.x + pf1.x + pf2.x + bfv.x;
                float s0 = d0.y + ps1.x + ps2.x + bsv.x;
                float f1 = d0.z + pf1.y + pf2.y + bfv.y;
                float s1 = d0.w + ps1.y + ps2.y + bsv.y;
                float f2 = d1.x + pf1.z + pf2.z + bfv.z;
                float s2 = d1.y + ps1.z + ps2.z + bsv.z;
                float f3 = d1.z + pf1.w + pf2.w + bfv.w;
                float s3 = d1.w + ps1.w + ps2.w + bsv.w;

                float m0 = sigmoidf_(f0) * softplusf_(s0);
                float m1 = sigmoidf_(f1) * softplusf_(s1);
                float m2 = sigmoidf_(f2) * softplusf_(s2);
                float m3 = sigmoidf_(f3) * softplusf_(s3);

                float* dst = g_agg + (size_t)sN * D + e_tc * 4;
                asm volatile("red.global.add.v4.f32 [%0], {%1, %2, %3, %4};"
                             :: "l"(dst), "f"(m0), "f"(m1), "f"(m2), "f"(m3) : "memory");
            }
            __syncthreads();   // D region consumed before next phase / next A store
        }
        tile = next;
    }
}

// ---------------- BN stats ----------------
__global__ __launch_bounds__(128) void bn_stats() {
    const int d = threadIdx.x;
    float sum = 0.f, sq = 0.f;
    for (int n = blockIdx.x; n < N_NODES; n += gridDim.x) {
        float v = g_agg[(size_t)n * D + d];
        sum += v;
        sq += v * v;
    }
    atomicAdd(&g_stats[d], sum);
    atomicAdd(&g_stats[D + d], sq);
}

// ---------------- BN apply + residual + softplus ----------------
__global__ __launch_bounds__(256) void final_kernel(
    const float* __restrict__ x, const float* __restrict__ gamma,
    const float* __restrict__ beta, float* __restrict__ out)
{
    const float invN = 1.0f / (float)N_NODES;
    for (size_t idx = (size_t)blockIdx.x * blockDim.x + threadIdx.x;
         idx < (size_t)N_NODES * D;
         idx += (size_t)gridDim.x * blockDim.x) {
        int d = (int)(idx & (D - 1));
        float mean = g_stats[d] * invN;
        float var = g_stats[D + d] * invN - mean * mean;
        float rstd = rsqrtf(var + BN_EPS);
        float a = (g_agg[idx] - mean) * rstd * gamma[d] + beta[d];
        out[idx] = softplusf_(x[idx] + a);
    }
}

// ---------------- launch ----------------
extern "C" void kernel_launch(void* const* d_in, const int* in_sizes, int n_in,
                              void* d_out, int out_size) {
    const float* x         = (const float*)d_in[0];
    const float* edge_attr = (const float*)d_in[1];
    const int*   edge_src  = (const int*)d_in[2];
    const int*   edge_tgt  = (const int*)d_in[3];
    const float* Wf        = (const float*)d_in[4];
    const float* bf        = (const float*)d_in[5];
    const float* Ws        = (const float*)d_in[6];
    const float* bs        = (const float*)d_in[7];
    const float* gamma     = (const float*)d_in[8];
    const float* beta      = (const float*)d_in[9];
    float* out = (float*)d_out;

    static bool attr_set = false;
    if (!attr_set) {
        cudaFuncSetAttribute(edge_fused_mma, cudaFuncAttributeMaxDynamicSharedMemorySize, EDGE_SMEM);
        cudaFuncSetAttribute(node_gemm_mma, cudaFuncAttributeMaxDynamicSharedMemorySize, NODE_SMEM);
        attr_set = true;
    }

    prep_weights<<<128, 256>>>(Wf, Ws);
    zero_scratch<<<4096, 256>>>();
    {
        dim3 grid(148, 2);
        node_gemm_mma<<<grid, 256, NODE_SMEM>>>(x);
    }
    edge_fused_mma<<<296, 256, EDGE_SMEM>>>(edge_attr, edge_src, edge_tgt, bf, bs);
    bn_stats<<<512, 128>>>();
    final_kernel<<<(N_NODES * D + 255) / 256, 256>>>(x, gamma, beta, out);
}

// round 13
// speedup vs baseline: 1.7362x; 1.1237x over previous
#include <cuda_runtime.h>
#include <cuda_bf16.h>
#include <cuda_fp16.h>
#include <math.h>
#include <stdint.h>

#define N_NODES 50000
#define N_EDGES 500000
#define D 128
#define BN_EPS 1e-5f

#define NT_EDGE ((N_EDGES + 63) / 64)   // 7813
#define NT_NODE ((N_NODES + 63) / 64)   // 782

// ---------------- scratch (static device globals; no allocation) ----------------
// P in fp16, gate-interleaved: [node][j], j<256: j=2c->f1_c (x@Wf_a), j=2c+1->s1_c (x@Ws_a);
// j>=256: (j-256)=2c->f2_c (x@Wf_b), 2c+1->s2_c (x@Ws_b).   51 MB -> L2-resident.
__device__ __align__(16) __half g_P16[(size_t)N_NODES * 512];
__device__ float g_agg[(size_t)N_NODES * D];     // scatter-sum target
__device__ float g_stats[2 * D];                 // [sum | sumsq]
// Edge-B fragments for mma.sync m16n8k16 (f16), hi term, fragment-linear:
// u32 index = (((kstep*32 + ntile)*32) + lane)*2 + reg
__device__ __align__(16) uint32_t g_Bfrag[8 * 32 * 32 * 2];      // 64 KB
// Node-B fragments ([k=128][n=512], interleaved-output layout as above)
__device__ __align__(16) uint32_t g_B1frag[8 * 64 * 32 * 2];     // 128 KB

// node output col j -> weight value at reduction row k
__device__ __forceinline__ float b1_val(const float* Wf, const float* Ws, int k, int j) {
    int c = (j & 255) >> 1;
    int krow = (j >= 256 ? 128 : 0) + k;
    const float* W = (j & 1) ? Ws : Wf;
    return W[krow * 128 + c];
}

// ---------------- weight repack ----------------
__global__ void prep_weights(const float* __restrict__ Wf, const float* __restrict__ Ws) {
    int i = blockIdx.x * blockDim.x + threadIdx.x;
    if (i < 16384) {
        int reg   = i & 1;
        int lane  = (i >> 1) & 31;
        int ntile = (i >> 6) & 31;
        int kstep = (i >> 11) & 7;
        int k0 = kstep * 16 + (lane & 3) * 2 + reg * 8;
        int n  = ntile * 8 + (lane >> 2);
        int c  = n >> 1;
        const float* W = (n & 1) ? Ws : Wf;
        __half h0 = __float2half_rn(W[(256 + k0) * 128 + c]);
        __half h1 = __float2half_rn(W[(256 + k0 + 1) * 128 + c]);
        g_Bfrag[i] = (uint32_t)__half_as_ushort(h0) | ((uint32_t)__half_as_ushort(h1) << 16);
    }
    if (i < 32768) {
        int reg   = i & 1;
        int lane  = (i >> 1) & 31;
        int ntile = (i >> 6) & 63;
        int kstep = (i >> 12) & 7;
        int k0 = kstep * 16 + (lane & 3) * 2 + reg * 8;
        int n  = ntile * 8 + (lane >> 2);
        __half h0 = __float2half_rn(b1_val(Wf, Ws, k0, n));
        __half h1 = __float2half_rn(b1_val(Wf, Ws, k0 + 1, n));
        g_B1frag[i] = (uint32_t)__half_as_ushort(h0) | ((uint32_t)__half_as_ushort(h1) << 16);
    }
}

// ---------------- zero scratch ----------------
__global__ void zero_scratch() {
    size_t n4 = (size_t)N_NODES * D / 4;
    float4* p = reinterpret_cast<float4*>(g_agg);
    for (size_t i = blockIdx.x * blockDim.x + threadIdx.x; i < n4; i += (size_t)gridDim.x * blockDim.x)
        p[i] = make_float4(0.f, 0.f, 0.f, 0.f);
    int t = blockIdx.x * blockDim.x + threadIdx.x;
    if (t < 2 * D) g_stats[t] = 0.f;
}

// ---------------- helpers ----------------
__device__ __forceinline__ float sigmoidf_(float x) { return 1.f / (1.f + expf(-x)); }
__device__ __forceinline__ float softplusf_(float x) {
    return fmaxf(x, 0.f) + log1pf(expf(-fabsf(x)));
}
__device__ __forceinline__ void mma_f16(float* d, uint32_t a0, uint32_t a1, uint32_t a2,
                                        uint32_t a3, uint32_t b0, uint32_t b1) {
    asm volatile(
        "mma.sync.aligned.m16n8k16.row.col.f32.f16.f16.f32 "
        "{%0,%1,%2,%3}, {%4,%5,%6,%7}, {%8,%9}, {%0,%1,%2,%3};"
        : "+f"(d[0]), "+f"(d[1]), "+f"(d[2]), "+f"(d[3])
        : "r"(a0), "r"(a1), "r"(a2), "r"(a3), "r"(b0), "r"(b1));
}
__device__ __forceinline__ void ldsm_x4(uint32_t& a0, uint32_t& a1, uint32_t& a2, uint32_t& a3,
                                        uint32_t saddr) {
    asm volatile("ldmatrix.sync.aligned.m8n8.x4.shared.b16 {%0,%1,%2,%3}, [%4];"
                 : "=r"(a0), "=r"(a1), "=r"(a2), "=r"(a3) : "r"(saddr));
}
__device__ __forceinline__ uint32_t smem_u32(const void* p) {
    uint32_t a;
    asm("{ .reg .u64 t; cvta.to.shared.u64 t, %1; cvt.u32.u64 %0, t; }" : "=r"(a) : "l"(p));
    return a;
}

// Load a 64x128 fp32 tile into registers (8 float4/thread); zero padding beyond M.
__device__ __forceinline__ void load_a_regs(const float* __restrict__ A, int row0, int M,
                                            int tid, float4* av) {
#pragma unroll
    for (int it = 0; it < 8; it++) {
        int lin = it * 256 + tid;
        int row = lin >> 5;
        int c4 = (lin & 31) << 2;
        int e = row0 + row;
        av[it] = make_float4(0.f, 0.f, 0.f, 0.f);
        if (e < M) av[it] = *reinterpret_cast<const float4*>(A + (size_t)e * 128 + c4);
    }
}
// Convert+split registers into hi/lo fp16 smem tiles (272B row stride).
__device__ __forceinline__ void store_a_split(const float4* av, char* ahi, char* alo, int tid) {
#pragma unroll
    for (int it = 0; it < 8; it++) {
        int lin = it * 256 + tid;
        int row = lin >> 5;
        int c4 = (lin & 31) << 2;
        float4 v = av[it];
        __half h0 = __float2half_rn(v.x), h1 = __float2half_rn(v.y);
        __half h2 = __float2half_rn(v.z), h3 = __float2half_rn(v.w);
        __half l0 = __float2half_rn(v.x - __half2float(h0));
        __half l1 = __float2half_rn(v.y - __half2float(h1));
        __half l2 = __float2half_rn(v.z - __half2float(h2));
        __half l3 = __float2half_rn(v.w - __half2float(h3));
        uint2 hp, lp;
        hp.x = (uint32_t)__half_as_ushort(h0) | ((uint32_t)__half_as_ushort(h1) << 16);
        hp.y = (uint32_t)__half_as_ushort(h2) | ((uint32_t)__half_as_ushort(h3) << 16);
        lp.x = (uint32_t)__half_as_ushort(l0) | ((uint32_t)__half_as_ushort(l1) << 16);
        lp.y = (uint32_t)__half_as_ushort(l2) | ((uint32_t)__half_as_ushort(l3) << 16);
        int off = row * 272 + c4 * 2;
        *reinterpret_cast<uint2*>(ahi + off) = hp;
        *reinterpret_cast<uint2*>(alo + off) = lp;
    }
}

// ---------------- persistent node GEMM: g_P16[M,512] = fp16(x @ B1) ----------------
#define NSM_AHI 0
#define NSM_ALO (64 * 272)
#define NSM_B   (2 * 64 * 272)
#define NODE_SMEM (NSM_B + 65536)

__global__ __launch_bounds__(256, 2) void node_gemm_mma(const float* __restrict__ X)
{
    extern __shared__ char basep[];
    const uint32_t sbase = smem_u32(basep);
    const int tid = threadIdx.x;
    const int wid = tid >> 5;
    const int lane = tid & 31;
    const int h = blockIdx.y;
    const int warpM = wid & 1;
    const int warpN = wid >> 1;

    // B slice once
    {
        int4* dst = reinterpret_cast<int4*>(basep + NSM_B);
        const int4* s = reinterpret_cast<const int4*>(g_B1frag);
#pragma unroll
        for (int it = 0; it < 16; it++) {
            int idx = it * 256 + tid;
            int kstep = idx >> 9;
            int within = idx & 511;
            dst[idx] = s[kstep * 1024 + h * 512 + within];
        }
    }

    int tile = blockIdx.x;
    float4 av[8];
    if (tile < NT_NODE) load_a_regs(X, tile * 64, N_NODES, tid, av);

    while (tile < NT_NODE) {
        store_a_split(av, basep + NSM_AHI, basep + NSM_ALO, tid);
        __syncthreads();

        float acc[2][8][4];
#pragma unroll
        for (int mt = 0; mt < 2; mt++)
#pragma unroll
            for (int nt = 0; nt < 8; nt++)
#pragma unroll
                for (int j = 0; j < 4; j++) acc[mt][nt][j] = 0.f;

        {
            const uint2* bp = reinterpret_cast<const uint2*>(basep + NSM_B);
            const uint32_t a_lane_off = (uint32_t)((lane & 15) * 272 + (lane >> 4) * 16);
#pragma unroll
            for (int kstep = 0; kstep < 8; kstep++) {
                uint2 bh[8];
#pragma unroll
                for (int nt = 0; nt < 8; nt++)
                    bh[nt] = bp[(kstep * 32 + warpN * 8 + nt) * 32 + lane];
#pragma unroll
                for (int mt = 0; mt < 2; mt++) {
                    uint32_t rowbase = (uint32_t)((warpM * 32 + mt * 16) * 272 + kstep * 32);
                    uint32_t ah0, ah1, ah2, ah3, al0, al1, al2, al3;
                    ldsm_x4(ah0, ah1, ah2, ah3, sbase + NSM_AHI + rowbase + a_lane_off);
                    ldsm_x4(al0, al1, al2, al3, sbase + NSM_ALO + rowbase + a_lane_off);
#pragma unroll
                    for (int nt = 0; nt < 8; nt++)
                        mma_f16(acc[mt][nt], ah0, ah1, ah2, ah3, bh[nt].x, bh[nt].y);
#pragma unroll
                    for (int nt = 0; nt < 8; nt++)
                        mma_f16(acc[mt][nt], al0, al1, al2, al3, bh[nt].x, bh[nt].y);
                }
            }
        }

        int row0 = tile * 64;
        int next = tile + gridDim.x;
        if (next < NT_NODE) load_a_regs(X, next * 64, N_NODES, tid, av);

        // fp16 store epilogue (col pairs adjacent)
#pragma unroll
        for (int mt = 0; mt < 2; mt++) {
            int rowl = warpM * 32 + mt * 16 + (lane >> 2);
#pragma unroll
            for (int nt = 0; nt < 8; nt++) {
                int col = h * 256 + warpN * 64 + nt * 8 + (lane & 3) * 2;
                int r0 = row0 + rowl;
                if (r0 < N_NODES) {
                    __half2 hv = __floats2half2_rn(acc[mt][nt][0], acc[mt][nt][1]);
                    *reinterpret_cast<__half2*>(g_P16 + (size_t)r0 * 512 + col) = hv;
                }
                int r1 = r0 + 8;
                if (r1 < N_NODES) {
                    __half2 hv = __floats2half2_rn(acc[mt][nt][2], acc[mt][nt][3]);
                    *reinterpret_cast<__half2*>(g_P16 + (size_t)r1 * 512 + col) = hv;
                }
            }
        }
        __syncthreads();
        tile = next;
    }
}

// ---------------- persistent fused edge GEMM + gate + scatter ----------------
#define SM_SRC 0
#define SM_TGT 256
#define SM_AHI 512
#define SM_ALO (512 + 64 * 272)
#define SM_B   (512 + 2 * 64 * 272)
#define SM_D   512
#define DSTRIDE 260
#define EDGE_SMEM (SM_B + 65536)

__global__ __launch_bounds__(256, 2) void edge_fused_mma(
    const float* __restrict__ A,
    const int* __restrict__ src, const int* __restrict__ tgt,
    const float* __restrict__ bf, const float* __restrict__ bs)
{
    extern __shared__ char basep[];
    const uint32_t sbase = smem_u32(basep);
    const int tid = threadIdx.x;
    const int wid = tid >> 5;
    const int lane = tid & 31;
    const int warpM = wid & 1;
    const int warpN = wid >> 1;

    int* s_src = reinterpret_cast<int*>(basep + SM_SRC);
    int* s_tgt = reinterpret_cast<int*>(basep + SM_TGT);

    // B table once per CTA
    {
        int4* dst = reinterpret_cast<int4*>(basep + SM_B);
        const int4* s = reinterpret_cast<const int4*>(g_Bfrag);
#pragma unroll
        for (int i = 0; i < 16; i++) dst[i * 256 + tid] = s[i * 256 + tid];
    }

    // epilogue constants
    const int e_tr = tid >> 5;
    const int e_tc = tid & 31;
    const float4 bfv = *reinterpret_cast<const float4*>(bf + e_tc * 4);
    const float4 bsv = *reinterpret_cast<const float4*>(bs + e_tc * 4);

    int tile = blockIdx.x;
    float4 av[8];
    int my_src = 0, my_tgt = 0;
    if (tile < NT_EDGE) {
        load_a_regs(A, tile * 64, N_EDGES, tid, av);
        if (tid < 64) {
            int r = tile * 64 + tid;
            my_src = (r < N_EDGES) ? src[r] : 0;
            my_tgt = (r < N_EDGES) ? tgt[r] : 0;
        }
    }

    while (tile < NT_EDGE) {
        store_a_split(av, basep + SM_AHI, basep + SM_ALO, tid);
        if (tid < 64) { s_src[tid] = my_src; s_tgt[tid] = my_tgt; }
        __syncthreads();

        float acc[2][8][4];
#pragma unroll
        for (int mt = 0; mt < 2; mt++)
#pragma unroll
            for (int nt = 0; nt < 8; nt++)
#pragma unroll
                for (int j = 0; j < 4; j++) acc[mt][nt][j] = 0.f;

        {
            const uint2* bp = reinterpret_cast<const uint2*>(basep + SM_B);
            const uint32_t a_lane_off = (uint32_t)((lane & 15) * 272 + (lane >> 4) * 16);
#pragma unroll
            for (int kstep = 0; kstep < 8; kstep++) {
                uint2 bh[8];
#pragma unroll
                for (int nt = 0; nt < 8; nt++)
                    bh[nt] = bp[(kstep * 32 + warpN * 8 + nt) * 32 + lane];
#pragma unroll
                for (int mt = 0; mt < 2; mt++) {
                    uint32_t rowbase = (uint32_t)((warpM * 32 + mt * 16) * 272 + kstep * 32);
                    uint32_t ah0, ah1, ah2, ah3, al0, al1, al2, al3;
                    ldsm_x4(ah0, ah1, ah2, ah3, sbase + SM_AHI + rowbase + a_lane_off);
                    ldsm_x4(al0, al1, al2, al3, sbase + SM_ALO + rowbase + a_lane_off);
#pragma unroll
                    for (int nt = 0; nt < 8; nt++)
                        mma_f16(acc[mt][nt], ah0, ah1, ah2, ah3, bh[nt].x, bh[nt].y);
#pragma unroll
                    for (int nt = 0; nt < 8; nt++)
                        mma_f16(acc[mt][nt], al0, al1, al2, al3, bh[nt].x, bh[nt].y);
                }
            }
        }
        __syncthreads();   // mainloop done; A region dead (acc live in regs)

        const int row0 = tile * 64;
        const int next = tile + gridDim.x;
        float* Dsm = reinterpret_cast<float*>(basep + SM_D);

#pragma unroll
        for (int phase = 0; phase < 2; phase++) {
            // stage rows [phase*32, phase*32+32)
            if (warpM == phase) {
#pragma unroll
                for (int mt = 0; mt < 2; mt++) {
                    int rowl = mt * 16 + (lane >> 2);
#pragma unroll
                    for (int nt = 0; nt < 8; nt++) {
                        int col = warpN * 64 + nt * 8 + (lane & 3) * 2;
                        float* p0 = Dsm + (size_t)rowl * DSTRIDE + col;
                        p0[0] = acc[mt][nt][0];
                        p0[1] = acc[mt][nt][1];
                        float* p1 = p0 + 8 * DSTRIDE;
                        p1[0] = acc[mt][nt][2];
                        p1[1] = acc[mt][nt][3];
                    }
                }
            }
            __syncthreads();

            if (phase == 1 && next < NT_EDGE) {
                load_a_regs(A, next * 64, N_EDGES, tid, av);
                if (tid < 64) {
                    int r = next * 64 + tid;
                    my_src = (r < N_EDGES) ? src[r] : 0;
                    my_tgt = (r < N_EDGES) ? tgt[r] : 0;
                }
            }

            // epilogue: gate + scatter for this phase's 32 rows
#pragma unroll
            for (int i = 0; i < 4; i++) {
                int lr = e_tr * 4 + i;
                int grow = phase * 32 + lr;
                int e = row0 + grow;
                if (e >= N_EDGES) break;
                int sN = s_src[grow];
                int tN = s_tgt[grow];
                const float* dp = Dsm + (size_t)lr * DSTRIDE + e_tc * 8;
                float4 d0 = *reinterpret_cast<const float4*>(dp);       // f0,s0,f1,s1
                float4 d1 = *reinterpret_cast<const float4*>(dp + 4);   // f2,s2,f3,s3

                // fp16 interleaved P gathers: 16B each = 4 (f,s) pairs
                uint4 svv = *reinterpret_cast<const uint4*>(g_P16 + (size_t)sN * 512 + e_tc * 8);
                uint4 tvv = *reinterpret_cast<const uint4*>(g_P16 + (size_t)tN * 512 + 256 + e_tc * 8);
                const __half2* sh = reinterpret_cast<const __half2*>(&svv);
                const __half2* th = reinterpret_cast<const __half2*>(&tvv);
                float2 a0 = __half22float2(sh[0]), a1 = __half22float2(sh[1]);
                float2 a2 = __half22float2(sh[2]), a3 = __half22float2(sh[3]);
                float2 b0 = __half22float2(th[0]), b1 = __half22float2(th[1]);
                float2 b2 = __half22float2(th[2]), b3 = __half22float2(th[3]);

                float f0 = d0.x + a0.x + b0.x + bfv.x;
                float s0 = d0.y + a0.y + b0.y + bsv.x;
                float f1 = d0.z + a1.x + b1.x + bfv.y;
                float s1 = d0.w + a1.y + b1.y + bsv.y;
                float f2 = d1.x + a2.x + b2.x + bfv.z;
                float s2 = d1.y + a2.y + b2.y + bsv.z;
                float f3 = d1.z + a3.x + b3.x + bfv.w;
                float s3 = d1.w + a3.y + b3.y + bsv.w;

                float m0 = sigmoidf_(f0) * softplusf_(s0);
                float m1 = sigmoidf_(f1) * softplusf_(s1);
                float m2 = sigmoidf_(f2) * softplusf_(s2);
                float m3 = sigmoidf_(f3) * softplusf_(s3);

                float* dst = g_agg + (size_t)sN * D + e_tc * 4;
                asm volatile("red.global.add.v4.f32 [%0], {%1, %2, %3, %4};"
                             :: "l"(dst), "f"(m0), "f"(m1), "f"(m2), "f"(m3) : "memory");
            }
            __syncthreads();
        }
        tile = next;
    }
}

// ---------------- BN stats ----------------
__global__ __launch_bounds__(128) void bn_stats() {
    const int d = threadIdx.x;
    float sum = 0.f, sq = 0.f;
    for (int n = blockIdx.x; n < N_NODES; n += gridDim.x) {
        float v = g_agg[(size_t)n * D + d];
        sum += v;
        sq += v * v;
    }
    atomicAdd(&g_stats[d], sum);
    atomicAdd(&g_stats[D + d], sq);
}

// ---------------- BN apply + residual + softplus ----------------
__global__ __launch_bounds__(256) void final_kernel(
    const float* __restrict__ x, const float* __restrict__ gamma,
    const float* __restrict__ beta, float* __restrict__ out)
{
    const float invN = 1.0f / (float)N_NODES;
    for (size_t idx = (size_t)blockIdx.x * blockDim.x + threadIdx.x;
         idx < (size_t)N_NODES * D;
         idx += (size_t)gridDim.x * blockDim.x) {
        int d = (int)(idx & (D - 1));
        float mean = g_stats[d] * invN;
        float var = g_stats[D + d] * invN - mean * mean;
        float rstd = rsqrtf(var + BN_EPS);
        float a = (g_agg[idx] - mean) * rstd * gamma[d] + beta[d];
        out[idx] = softplusf_(x[idx] + a);
    }
}

// ---------------- launch ----------------
extern "C" void kernel_launch(void* const* d_in, const int* in_sizes, int n_in,
                              void* d_out, int out_size) {
    const float* x         = (const float*)d_in[0];
    const float* edge_attr = (const float*)d_in[1];
    const int*   edge_src  = (const int*)d_in[2];
    const int*   edge_tgt  = (const int*)d_in[3];
    const float* Wf        = (const float*)d_in[4];
    const float* bf        = (const float*)d_in[5];
    const float* Ws        = (const float*)d_in[6];
    const float* bs        = (const float*)d_in[7];
    const float* gamma     = (const float*)d_in[8];
    const float* beta      = (const float*)d_in[9];
    float* out = (float*)d_out;

    static bool attr_set = false;
    if (!attr_set) {
        cudaFuncSetAttribute(edge_fused_mma, cudaFuncAttributeMaxDynamicSharedMemorySize, EDGE_SMEM);
        cudaFuncSetAttribute(node_gemm_mma, cudaFuncAttributeMaxDynamicSharedMemorySize, NODE_SMEM);
        attr_set = true;
    }

    prep_weights<<<128, 256>>>(Wf, Ws);
    zero_scratch<<<4096, 256>>>();
    {
        dim3 grid(148, 2);
        node_gemm_mma<<<grid, 256, NODE_SMEM>>>(x);
    }
    edge_fused_mma<<<296, 256, EDGE_SMEM>>>(edge_attr, edge_src, edge_tgt, bf, bs);
    bn_stats<<<512, 128>>>();
    final_kernel<<<(N_NODES * D + 255) / 256, 256>>>(x, gamma, beta, out);
}

// round 14
// speedup vs baseline: 1.9413x; 1.1181x over previous
#include <cuda_runtime.h>
#include <cuda_bf16.h>
#include <cuda_fp16.h>
#include <math.h>
#include <stdint.h>

#define N_NODES 50000
#define N_EDGES 500000
#define D 128
#define BN_EPS 1e-5f

#define NT_EDGE ((N_EDGES + 63) / 64)   // 7813
#define NT_NODE ((N_NODES + 63) / 64)   // 782

// ---------------- scratch (static device globals; no allocation) ----------------
// P in fp16, gate-interleaved: [node][j], j<256: j=2c->f1_c, j=2c+1->s1_c;
// j>=256: (j-256)=2c->f2_c, 2c+1->s2_c.   51 MB -> L2-resident.
__device__ __align__(16) __half g_P16[(size_t)N_NODES * 512];
__device__ float g_agg[(size_t)N_NODES * D];     // scatter-sum target
__device__ float g_stats[2 * D];                 // [sum | sumsq]
// Edge-B fragments for mma.sync m16n8k16 (f16), hi term, fragment-linear:
// u32 index = (((kstep*32 + ntile)*32) + lane)*2 + reg
__device__ __align__(16) uint32_t g_Bfrag[8 * 32 * 32 * 2];      // 64 KB
// Node-B fragments ([k=128][n=512], interleaved-output layout)
__device__ __align__(16) uint32_t g_B1frag[8 * 64 * 32 * 2];     // 128 KB

// node output col j -> weight value at reduction row k
__device__ __forceinline__ float b1_val(const float* Wf, const float* Ws, int k, int j) {
    int c = (j & 255) >> 1;
    int krow = (j >= 256 ? 128 : 0) + k;
    const float* W = (j & 1) ? Ws : Wf;
    return W[krow * 128 + c];
}

// ---------------- weight repack ----------------
__global__ void prep_weights(const float* __restrict__ Wf, const float* __restrict__ Ws) {
    int i = blockIdx.x * blockDim.x + threadIdx.x;
    if (i < 16384) {
        int reg   = i & 1;
        int lane  = (i >> 1) & 31;
        int ntile = (i >> 6) & 31;
        int kstep = (i >> 11) & 7;
        int k0 = kstep * 16 + (lane & 3) * 2 + reg * 8;
        int n  = ntile * 8 + (lane >> 2);
        int c  = n >> 1;
        const float* W = (n & 1) ? Ws : Wf;
        __half h0 = __float2half_rn(W[(256 + k0) * 128 + c]);
        __half h1 = __float2half_rn(W[(256 + k0 + 1) * 128 + c]);
        g_Bfrag[i] = (uint32_t)__half_as_ushort(h0) | ((uint32_t)__half_as_ushort(h1) << 16);
    }
    if (i < 32768) {
        int reg   = i & 1;
        int lane  = (i >> 1) & 31;
        int ntile = (i >> 6) & 63;
        int kstep = (i >> 12) & 7;
        int k0 = kstep * 16 + (lane & 3) * 2 + reg * 8;
        int n  = ntile * 8 + (lane >> 2);
        __half h0 = __float2half_rn(b1_val(Wf, Ws, k0, n));
        __half h1 = __float2half_rn(b1_val(Wf, Ws, k0 + 1, n));
        g_B1frag[i] = (uint32_t)__half_as_ushort(h0) | ((uint32_t)__half_as_ushort(h1) << 16);
    }
}

// ---------------- zero scratch ----------------
__global__ void zero_scratch() {
    size_t n4 = (size_t)N_NODES * D / 4;
    float4* p = reinterpret_cast<float4*>(g_agg);
    for (size_t i = blockIdx.x * blockDim.x + threadIdx.x; i < n4; i += (size_t)gridDim.x * blockDim.x)
        p[i] = make_float4(0.f, 0.f, 0.f, 0.f);
    int t = blockIdx.x * blockDim.x + threadIdx.x;
    if (t < 2 * D) g_stats[t] = 0.f;
}

// ---------------- helpers ----------------
// fast gates: MUFU-based. args are O(1); saturation cases degrade gracefully.
__device__ __forceinline__ float fast_sigmoid(float x) {
    return __fdividef(1.f, 1.f + __expf(-x));
}
__device__ __forceinline__ float fast_softplus(float x) {
    return fmaxf(x, 0.f) + __logf(1.f + __expf(-fabsf(x)));
}
__device__ __forceinline__ void mma_f16(float* d, uint32_t a0, uint32_t a1, uint32_t a2,
                                        uint32_t a3, uint32_t b0, uint32_t b1) {
    asm volatile(
        "mma.sync.aligned.m16n8k16.row.col.f32.f16.f16.f32 "
        "{%0,%1,%2,%3}, {%4,%5,%6,%7}, {%8,%9}, {%0,%1,%2,%3};"
        : "+f"(d[0]), "+f"(d[1]), "+f"(d[2]), "+f"(d[3])
        : "r"(a0), "r"(a1), "r"(a2), "r"(a3), "r"(b0), "r"(b1));
}
__device__ __forceinline__ void ldsm_x4(uint32_t& a0, uint32_t& a1, uint32_t& a2, uint32_t& a3,
                                        uint32_t saddr) {
    asm volatile("ldmatrix.sync.aligned.m8n8.x4.shared.b16 {%0,%1,%2,%3}, [%4];"
                 : "=r"(a0), "=r"(a1), "=r"(a2), "=r"(a3) : "r"(saddr));
}
__device__ __forceinline__ uint32_t smem_u32(const void* p) {
    uint32_t a;
    asm("{ .reg .u64 t; cvta.to.shared.u64 t, %1; cvt.u32.u64 %0, t; }" : "=r"(a) : "l"(p));
    return a;
}

// Load a 64x128 fp32 tile into registers (8 float4/thread); zero padding beyond M.
__device__ __forceinline__ void load_a_regs(const float* __restrict__ A, int row0, int M,
                                            int tid, float4* av) {
#pragma unroll
    for (int it = 0; it < 8; it++) {
        int lin = it * 256 + tid;
        int row = lin >> 5;
        int c4 = (lin & 31) << 2;
        int e = row0 + row;
        av[it] = make_float4(0.f, 0.f, 0.f, 0.f);
        if (e < M) av[it] = *reinterpret_cast<const float4*>(A + (size_t)e * 128 + c4);
    }
}
// Convert+split registers into hi/lo fp16 smem tiles (272B row stride).
__device__ __forceinline__ void store_a_split(const float4* av, char* ahi, char* alo, int tid) {
#pragma unroll
    for (int it = 0; it < 8; it++) {
        int lin = it * 256 + tid;
        int row = lin >> 5;
        int c4 = (lin & 31) << 2;
        float4 v = av[it];
        __half h0 = __float2half_rn(v.x), h1 = __float2half_rn(v.y);
        __half h2 = __float2half_rn(v.z), h3 = __float2half_rn(v.w);
        __half l0 = __float2half_rn(v.x - __half2float(h0));
        __half l1 = __float2half_rn(v.y - __half2float(h1));
        __half l2 = __float2half_rn(v.z - __half2float(h2));
        __half l3 = __float2half_rn(v.w - __half2float(h3));
        uint2 hp, lp;
        hp.x = (uint32_t)__half_as_ushort(h0) | ((uint32_t)__half_as_ushort(h1) << 16);
        hp.y = (uint32_t)__half_as_ushort(h2) | ((uint32_t)__half_as_ushort(h3) << 16);
        lp.x = (uint32_t)__half_as_ushort(l0) | ((uint32_t)__half_as_ushort(l1) << 16);
        lp.y = (uint32_t)__half_as_ushort(l2) | ((uint32_t)__half_as_ushort(l3) << 16);
        int off = row * 272 + c4 * 2;
        *reinterpret_cast<uint2*>(ahi + off) = hp;
        *reinterpret_cast<uint2*>(alo + off) = lp;
    }
}

// ---------------- persistent node GEMM: g_P16[M,512] = fp16(x @ B1) ----------------
#define NSM_AHI 0
#define NSM_ALO (64 * 272)
#define NSM_B   (2 * 64 * 272)
#define NODE_SMEM (NSM_B + 65536)

__global__ __launch_bounds__(256, 2) void node_gemm_mma(const float* __restrict__ X)
{
    extern __shared__ char basep[];
    const uint32_t sbase = smem_u32(basep);
    const int tid = threadIdx.x;
    const int wid = tid >> 5;
    const int lane = tid & 31;
    const int h = blockIdx.y;
    const int warpM = wid & 1;
    const int warpN = wid >> 1;

    // B slice once
    {
        int4* dst = reinterpret_cast<int4*>(basep + NSM_B);
        const int4* s = reinterpret_cast<const int4*>(g_B1frag);
#pragma unroll
        for (int it = 0; it < 16; it++) {
            int idx = it * 256 + tid;
            int kstep = idx >> 9;
            int within = idx & 511;
            dst[idx] = s[kstep * 1024 + h * 512 + within];
        }
    }

    int tile = blockIdx.x;
    float4 av[8];
    if (tile < NT_NODE) load_a_regs(X, tile * 64, N_NODES, tid, av);

    while (tile < NT_NODE) {
        store_a_split(av, basep + NSM_AHI, basep + NSM_ALO, tid);
        __syncthreads();

        float acc[2][8][4];
#pragma unroll
        for (int mt = 0; mt < 2; mt++)
#pragma unroll
            for (int nt = 0; nt < 8; nt++)
#pragma unroll
                for (int j = 0; j < 4; j++) acc[mt][nt][j] = 0.f;

        {
            const uint2* bp = reinterpret_cast<const uint2*>(basep + NSM_B);
            const uint32_t a_lane_off = (uint32_t)((lane & 15) * 272 + (lane >> 4) * 16);
#pragma unroll
            for (int kstep = 0; kstep < 8; kstep++) {
                uint2 bh[8];
#pragma unroll
                for (int nt = 0; nt < 8; nt++)
                    bh[nt] = bp[(kstep * 32 + warpN * 8 + nt) * 32 + lane];
#pragma unroll
                for (int mt = 0; mt < 2; mt++) {
                    uint32_t rowbase = (uint32_t)((warpM * 32 + mt * 16) * 272 + kstep * 32);
                    uint32_t ah0, ah1, ah2, ah3, al0, al1, al2, al3;
                    ldsm_x4(ah0, ah1, ah2, ah3, sbase + NSM_AHI + rowbase + a_lane_off);
                    ldsm_x4(al0, al1, al2, al3, sbase + NSM_ALO + rowbase + a_lane_off);
#pragma unroll
                    for (int nt = 0; nt < 8; nt++)
                        mma_f16(acc[mt][nt], ah0, ah1, ah2, ah3, bh[nt].x, bh[nt].y);
#pragma unroll
                    for (int nt = 0; nt < 8; nt++)
                        mma_f16(acc[mt][nt], al0, al1, al2, al3, bh[nt].x, bh[nt].y);
                }
            }
        }

        int row0 = tile * 64;
        int next = tile + gridDim.x;
        if (next < NT_NODE) load_a_regs(X, next * 64, N_NODES, tid, av);

        // fp16 store epilogue (col pairs adjacent)
#pragma unroll
        for (int mt = 0; mt < 2; mt++) {
            int rowl = warpM * 32 + mt * 16 + (lane >> 2);
#pragma unroll
            for (int nt = 0; nt < 8; nt++) {
                int col = h * 256 + warpN * 64 + nt * 8 + (lane & 3) * 2;
                int r0 = row0 + rowl;
                if (r0 < N_NODES) {
                    __half2 hv = __floats2half2_rn(acc[mt][nt][0], acc[mt][nt][1]);
                    *reinterpret_cast<__half2*>(g_P16 + (size_t)r0 * 512 + col) = hv;
                }
                int r1 = r0 + 8;
                if (r1 < N_NODES) {
                    __half2 hv = __floats2half2_rn(acc[mt][nt][2], acc[mt][nt][3]);
                    *reinterpret_cast<__half2*>(g_P16 + (size_t)r1 * 512 + col) = hv;
                }
            }
        }
        __syncthreads();
        tile = next;
    }
}

// ---------------- persistent fused edge GEMM + gate + scatter ----------------
#define SM_SRC 0
#define SM_TGT 256
#define SM_AHI 512
#define SM_ALO (512 + 64 * 272)
#define SM_B   (512 + 2 * 64 * 272)
#define SM_D   512
#define DSTRIDE 260
#define EDGE_SMEM (SM_B + 65536)

__global__ __launch_bounds__(256, 2) void edge_fused_mma(
    const float* __restrict__ A,
    const int* __restrict__ src, const int* __restrict__ tgt,
    const float* __restrict__ bf, const float* __restrict__ bs)
{
    extern __shared__ char basep[];
    const uint32_t sbase = smem_u32(basep);
    const int tid = threadIdx.x;
    const int wid = tid >> 5;
    const int lane = tid & 31;
    const int warpM = wid & 1;
    const int warpN = wid >> 1;

    int* s_src = reinterpret_cast<int*>(basep + SM_SRC);
    int* s_tgt = reinterpret_cast<int*>(basep + SM_TGT);

    // B table once per CTA
    {
        int4* dst = reinterpret_cast<int4*>(basep + SM_B);
        const int4* s = reinterpret_cast<const int4*>(g_Bfrag);
#pragma unroll
        for (int i = 0; i < 16; i++) dst[i * 256 + tid] = s[i * 256 + tid];
    }

    // epilogue constants
    const int e_tr = tid >> 5;
    const int e_tc = tid & 31;
    const float4 bfv = *reinterpret_cast<const float4*>(bf + e_tc * 4);
    const float4 bsv = *reinterpret_cast<const float4*>(bs + e_tc * 4);

    int tile = blockIdx.x;
    float4 av[8];
    int my_src = 0, my_tgt = 0;
    if (tile < NT_EDGE) {
        load_a_regs(A, tile * 64, N_EDGES, tid, av);
        if (tid < 64) {
            int r = tile * 64 + tid;
            my_src = (r < N_EDGES) ? src[r] : 0;
            my_tgt = (r < N_EDGES) ? tgt[r] : 0;
        }
    }

    while (tile < NT_EDGE) {
        store_a_split(av, basep + SM_AHI, basep + SM_ALO, tid);
        if (tid < 64) { s_src[tid] = my_src; s_tgt[tid] = my_tgt; }
        __syncthreads();

        float acc[2][8][4];
#pragma unroll
        for (int mt = 0; mt < 2; mt++)
#pragma unroll
            for (int nt = 0; nt < 8; nt++)
#pragma unroll
                for (int j = 0; j < 4; j++) acc[mt][nt][j] = 0.f;

        {
            const uint2* bp = reinterpret_cast<const uint2*>(basep + SM_B);
            const uint32_t a_lane_off = (uint32_t)((lane & 15) * 272 + (lane >> 4) * 16);
#pragma unroll
            for (int kstep = 0; kstep < 8; kstep++) {
                uint2 bh[8];
#pragma unroll
                for (int nt = 0; nt < 8; nt++)
                    bh[nt] = bp[(kstep * 32 + warpN * 8 + nt) * 32 + lane];
#pragma unroll
                for (int mt = 0; mt < 2; mt++) {
                    uint32_t rowbase = (uint32_t)((warpM * 32 + mt * 16) * 272 + kstep * 32);
                    uint32_t ah0, ah1, ah2, ah3, al0, al1, al2, al3;
                    ldsm_x4(ah0, ah1, ah2, ah3, sbase + SM_AHI + rowbase + a_lane_off);
                    ldsm_x4(al0, al1, al2, al3, sbase + SM_ALO + rowbase + a_lane_off);
#pragma unroll
                    for (int nt = 0; nt < 8; nt++)
                        mma_f16(acc[mt][nt], ah0, ah1, ah2, ah3, bh[nt].x, bh[nt].y);
#pragma unroll
                    for (int nt = 0; nt < 8; nt++)
                        mma_f16(acc[mt][nt], al0, al1, al2, al3, bh[nt].x, bh[nt].y);
                }
            }
        }
        __syncthreads();   // mainloop done; A region dead (acc live in regs)

        const int row0 = tile * 64;
        const int next = tile + gridDim.x;
        float* Dsm = reinterpret_cast<float*>(basep + SM_D);

#pragma unroll
        for (int phase = 0; phase < 2; phase++) {
            // stage rows [phase*32, phase*32+32)
            if (warpM == phase) {
#pragma unroll
                for (int mt = 0; mt < 2; mt++) {
                    int rowl = mt * 16 + (lane >> 2);
#pragma unroll
                    for (int nt = 0; nt < 8; nt++) {
                        int col = warpN * 64 + nt * 8 + (lane & 3) * 2;
                        float* p0 = Dsm + (size_t)rowl * DSTRIDE + col;
                        p0[0] = acc[mt][nt][0];
                        p0[1] = acc[mt][nt][1];
                        float* p1 = p0 + 8 * DSTRIDE;
                        p1[0] = acc[mt][nt][2];
                        p1[1] = acc[mt][nt][3];
                    }
                }
            }
            __syncthreads();

            if (phase == 1 && next < NT_EDGE) {
                load_a_regs(A, next * 64, N_EDGES, tid, av);
                if (tid < 64) {
                    int r = next * 64 + tid;
                    my_src = (r < N_EDGES) ? src[r] : 0;
                    my_tgt = (r < N_EDGES) ? tgt[r] : 0;
                }
            }

            // epilogue: fast gate + scatter for this phase's 32 rows
#pragma unroll
            for (int i = 0; i < 4; i++) {
                int lr = e_tr * 4 + i;
                int grow = phase * 32 + lr;
                int e = row0 + grow;
                if (e >= N_EDGES) break;
                int sN = s_src[grow];
                int tN = s_tgt[grow];
                const float* dp = Dsm + (size_t)lr * DSTRIDE + e_tc * 8;
                float4 d0 = *reinterpret_cast<const float4*>(dp);       // f0,s0,f1,s1
                float4 d1 = *reinterpret_cast<const float4*>(dp + 4);   // f2,s2,f3,s3

                // fp16 interleaved P gathers: 16B each = 4 (f,s) pairs
                uint4 svv = *reinterpret_cast<const uint4*>(g_P16 + (size_t)sN * 512 + e_tc * 8);
                uint4 tvv = *reinterpret_cast<const uint4*>(g_P16 + (size_t)tN * 512 + 256 + e_tc * 8);
                const __half2* sh = reinterpret_cast<const __half2*>(&svv);
                const __half2* th = reinterpret_cast<const __half2*>(&tvv);
                float2 a0 = __half22float2(sh[0]), a1 = __half22float2(sh[1]);
                float2 a2 = __half22float2(sh[2]), a3 = __half22float2(sh[3]);
                float2 b0 = __half22float2(th[0]), b1 = __half22float2(th[1]);
                float2 b2 = __half22float2(th[2]), b3 = __half22float2(th[3]);

                float f0 = d0.x + a0.x + b0.x + bfv.x;
                float s0 = d0.y + a0.y + b0.y + bsv.x;
                float f1 = d0.z + a1.x + b1.x + bfv.y;
                float s1 = d0.w + a1.y + b1.y + bsv.y;
                float f2 = d1.x + a2.x + b2.x + bfv.z;
                float s2 = d1.y + a2.y + b2.y + bsv.z;
                float f3 = d1.z + a3.x + b3.x + bfv.w;
                float s3 = d1.w + a3.y + b3.y + bsv.w;

                float m0 = fast_sigmoid(f0) * fast_softplus(s0);
                float m1 = fast_sigmoid(f1) * fast_softplus(s1);
                float m2 = fast_sigmoid(f2) * fast_softplus(s2);
                float m3 = fast_sigmoid(f3) * fast_softplus(s3);

                float* dst = g_agg + (size_t)sN * D + e_tc * 4;
                asm volatile("red.global.add.v4.f32 [%0], {%1, %2, %3, %4};"
                             :: "l"(dst), "f"(m0), "f"(m1), "f"(m2), "f"(m3) : "memory");
            }
            __syncthreads();
        }
        tile = next;
    }
}

// ---------------- BN stats ----------------
__global__ __launch_bounds__(128) void bn_stats() {
    const int d = threadIdx.x;
    float sum = 0.f, sq = 0.f;
    for (int n = blockIdx.x; n < N_NODES; n += gridDim.x) {
        float v = g_agg[(size_t)n * D + d];
        sum += v;
        sq += v * v;
    }
    atomicAdd(&g_stats[d], sum);
    atomicAdd(&g_stats[D + d], sq);
}

// ---------------- BN apply + residual + softplus ----------------
__global__ __launch_bounds__(256) void final_kernel(
    const float* __restrict__ x, const float* __restrict__ gamma,
    const float* __restrict__ beta, float* __restrict__ out)
{
    const float invN = 1.0f / (float)N_NODES;
    for (size_t idx = (size_t)blockIdx.x * blockDim.x + threadIdx.x;
         idx < (size_t)N_NODES * D;
         idx += (size_t)gridDim.x * blockDim.x) {
        int d = (int)(idx & (D - 1));
        float mean = g_stats[d] * invN;
        float var = g_stats[D + d] * invN - mean * mean;
        float rstd = rsqrtf(var + BN_EPS);
        float a = (g_agg[idx] - mean) * rstd * gamma[d] + beta[d];
        out[idx] = fast_softplus(x[idx] + a);
    }
}

// ---------------- launch ----------------
extern "C" void kernel_launch(void* const* d_in, const int* in_sizes, int n_in,
                              void* d_out, int out_size) {
    const float* x         = (const float*)d_in[0];
    const float* edge_attr = (const float*)d_in[1];
    const int*   edge_src  = (const int*)d_in[2];
    const int*   edge_tgt  = (const int*)d_in[3];
    const float* Wf        = (const float*)d_in[4];
    const float* bf        = (const float*)d_in[5];
    const float* Ws        = (const float*)d_in[6];
    const float* bs        = (const float*)d_in[7];
    const float* gamma     = (const float*)d_in[8];
    const float* beta      = (const float*)d_in[9];
    float* out = (float*)d_out;

    static bool attr_set = false;
    if (!attr_set) {
        cudaFuncSetAttribute(edge_fused_mma, cudaFuncAttributeMaxDynamicSharedMemorySize, EDGE_SMEM);
        cudaFuncSetAttribute(node_gemm_mma, cudaFuncAttributeMaxDynamicSharedMemorySize, NODE_SMEM);
        attr_set = true;
    }

    prep_weights<<<128, 256>>>(Wf, Ws);
    zero_scratch<<<4096, 256>>>();
    {
        dim3 grid(148, 2);
        node_gemm_mma<<<grid, 256, NODE_SMEM>>>(x);
    }
    edge_fused_mma<<<296, 256, EDGE_SMEM>>>(edge_attr, edge_src, edge_tgt, bf, bs);
    bn_stats<<<512, 128>>>();
    final_kernel<<<(N_NODES * D + 255) / 256, 256>>>(x, gamma, beta, out);
}

// round 15
// speedup vs baseline: 1.9862x; 1.0232x over previous
#include <cuda_runtime.h>
#include <cuda_bf16.h>
#include <cuda_fp16.h>
#include <math.h>
#include <stdint.h>

#define N_NODES 50000
#define N_EDGES 500000
#define D 128
#define BN_EPS 1e-5f

#define NT_EDGE ((N_EDGES + 63) / 64)   // 7813
#define NT_NODE ((N_NODES + 63) / 64)   // 782

// ---------------- scratch (static device globals; no allocation) ----------------
// P in fp16, gate-interleaved: [node][j], j<256: j=2c->f1_c, j=2c+1->s1_c;
// j>=256: (j-256)=2c->f2_c, 2c+1->s2_c.   51 MB -> L2-resident.
__device__ __align__(16) __half g_P16[(size_t)N_NODES * 512];
__device__ float g_agg[(size_t)N_NODES * D];     // scatter-sum target
__device__ float g_stats[2 * D];                 // [sum | sumsq]
// Edge-B fragments for mma.sync m16n8k16 (f16), hi term, fragment-linear:
// u32 index = (((kstep*32 + ntile)*32) + lane)*2 + reg
__device__ __align__(16) uint32_t g_Bfrag[8 * 32 * 32 * 2];      // 64 KB
// Node-B fragments ([k=128][n=512], interleaved-output layout)
__device__ __align__(16) uint32_t g_B1frag[8 * 64 * 32 * 2];     // 128 KB

// node output col j -> weight value at reduction row k
__device__ __forceinline__ float b1_val(const float* Wf, const float* Ws, int k, int j) {
    int c = (j & 255) >> 1;
    int krow = (j >= 256 ? 128 : 0) + k;
    const float* W = (j & 1) ? Ws : Wf;
    return W[krow * 128 + c];
}

// ---------------- weight repack ----------------
__global__ void prep_weights(const float* __restrict__ Wf, const float* __restrict__ Ws) {
    int i = blockIdx.x * blockDim.x + threadIdx.x;
    if (i < 16384) {
        int reg   = i & 1;
        int lane  = (i >> 1) & 31;
        int ntile = (i >> 6) & 31;
        int kstep = (i >> 11) & 7;
        int k0 = kstep * 16 + (lane & 3) * 2 + reg * 8;
        int n  = ntile * 8 + (lane >> 2);
        int c  = n >> 1;
        const float* W = (n & 1) ? Ws : Wf;
        __half h0 = __float2half_rn(W[(256 + k0) * 128 + c]);
        __half h1 = __float2half_rn(W[(256 + k0 + 1) * 128 + c]);
        g_Bfrag[i] = (uint32_t)__half_as_ushort(h0) | ((uint32_t)__half_as_ushort(h1) << 16);
    }
    if (i < 32768) {
        int reg   = i & 1;
        int lane  = (i >> 1) & 31;
        int ntile = (i >> 6) & 63;
        int kstep = (i >> 12) & 7;
        int k0 = kstep * 16 + (lane & 3) * 2 + reg * 8;
        int n  = ntile * 8 + (lane >> 2);
        __half h0 = __float2half_rn(b1_val(Wf, Ws, k0, n));
        __half h1 = __float2half_rn(b1_val(Wf, Ws, k0 + 1, n));
        g_B1frag[i] = (uint32_t)__half_as_ushort(h0) | ((uint32_t)__half_as_ushort(h1) << 16);
    }
}

// ---------------- zero scratch ----------------
__global__ void zero_scratch() {
    size_t n4 = (size_t)N_NODES * D / 4;
    float4* p = reinterpret_cast<float4*>(g_agg);
    for (size_t i = blockIdx.x * blockDim.x + threadIdx.x; i < n4; i += (size_t)gridDim.x * blockDim.x)
        p[i] = make_float4(0.f, 0.f, 0.f, 0.f);
    int t = blockIdx.x * blockDim.x + threadIdx.x;
    if (t < 2 * D) g_stats[t] = 0.f;
}

// ---------------- helpers ----------------
__device__ __forceinline__ float fast_sigmoid(float x) {
    return __fdividef(1.f, 1.f + __expf(-x));
}
__device__ __forceinline__ float fast_softplus(float x) {
    return fmaxf(x, 0.f) + __logf(1.f + __expf(-fabsf(x)));
}
__device__ __forceinline__ void mma_f16(float* d, uint32_t a0, uint32_t a1, uint32_t a2,
                                        uint32_t a3, uint32_t b0, uint32_t b1) {
    asm volatile(
        "mma.sync.aligned.m16n8k16.row.col.f32.f16.f16.f32 "
        "{%0,%1,%2,%3}, {%4,%5,%6,%7}, {%8,%9}, {%0,%1,%2,%3};"
        : "+f"(d[0]), "+f"(d[1]), "+f"(d[2]), "+f"(d[3])
        : "r"(a0), "r"(a1), "r"(a2), "r"(a3), "r"(b0), "r"(b1));
}
__device__ __forceinline__ void ldsm_x4(uint32_t& a0, uint32_t& a1, uint32_t& a2, uint32_t& a3,
                                        uint32_t saddr) {
    asm volatile("ldmatrix.sync.aligned.m8n8.x4.shared.b16 {%0,%1,%2,%3}, [%4];"
                 : "=r"(a0), "=r"(a1), "=r"(a2), "=r"(a3) : "r"(saddr));
}
__device__ __forceinline__ uint32_t smem_u32(const void* p) {
    uint32_t a;
    asm("{ .reg .u64 t; cvta.to.shared.u64 t, %1; cvt.u32.u64 %0, t; }" : "=r"(a) : "l"(p));
    return a;
}

// Load a 64x128 fp32 tile into registers (8 float4/thread); zero padding beyond M.
__device__ __forceinline__ void load_a_regs(const float* __restrict__ A, int row0, int M,
                                            int tid, float4* av) {
#pragma unroll
    for (int it = 0; it < 8; it++) {
        int lin = it * 256 + tid;
        int row = lin >> 5;
        int c4 = (lin & 31) << 2;
        int e = row0 + row;
        av[it] = make_float4(0.f, 0.f, 0.f, 0.f);
        if (e < M) av[it] = *reinterpret_cast<const float4*>(A + (size_t)e * 128 + c4);
    }
}
// Convert+split registers into hi/lo fp16 smem tiles (272B row stride).
__device__ __forceinline__ void store_a_split(const float4* av, char* ahi, char* alo, int tid) {
#pragma unroll
    for (int it = 0; it < 8; it++) {
        int lin = it * 256 + tid;
        int row = lin >> 5;
        int c4 = (lin & 31) << 2;
        float4 v = av[it];
        __half h0 = __float2half_rn(v.x), h1 = __float2half_rn(v.y);
        __half h2 = __float2half_rn(v.z), h3 = __float2half_rn(v.w);
        __half l0 = __float2half_rn(v.x - __half2float(h0));
        __half l1 = __float2half_rn(v.y - __half2float(h1));
        __half l2 = __float2half_rn(v.z - __half2float(h2));
        __half l3 = __float2half_rn(v.w - __half2float(h3));
        uint2 hp, lp;
        hp.x = (uint32_t)__half_as_ushort(h0) | ((uint32_t)__half_as_ushort(h1) << 16);
        hp.y = (uint32_t)__half_as_ushort(h2) | ((uint32_t)__half_as_ushort(h3) << 16);
        lp.x = (uint32_t)__half_as_ushort(l0) | ((uint32_t)__half_as_ushort(l1) << 16);
        lp.y = (uint32_t)__half_as_ushort(l2) | ((uint32_t)__half_as_ushort(l3) << 16);
        int off = row * 272 + c4 * 2;
        *reinterpret_cast<uint2*>(ahi + off) = hp;
        *reinterpret_cast<uint2*>(alo + off) = lp;
    }
}

// ---------------- persistent node GEMM: g_P16[M,512] = fp16(x @ B1) ----------------
#define NSM_AHI 0
#define NSM_ALO (64 * 272)
#define NSM_B   (2 * 64 * 272)
#define NODE_SMEM (NSM_B + 65536)

__global__ __launch_bounds__(256, 2) void node_gemm_mma(const float* __restrict__ X)
{
    extern __shared__ char basep[];
    const uint32_t sbase = smem_u32(basep);
    const int tid = threadIdx.x;
    const int wid = tid >> 5;
    const int lane = tid & 31;
    const int h = blockIdx.y;
    const int warpM = wid & 1;
    const int warpN = wid >> 1;

    // B slice once
    {
        int4* dst = reinterpret_cast<int4*>(basep + NSM_B);
        const int4* s = reinterpret_cast<const int4*>(g_B1frag);
#pragma unroll
        for (int it = 0; it < 16; it++) {
            int idx = it * 256 + tid;
            int kstep = idx >> 9;
            int within = idx & 511;
            dst[idx] = s[kstep * 1024 + h * 512 + within];
        }
    }

    int tile = blockIdx.x;
    float4 av[8];
    if (tile < NT_NODE) load_a_regs(X, tile * 64, N_NODES, tid, av);

    while (tile < NT_NODE) {
        store_a_split(av, basep + NSM_AHI, basep + NSM_ALO, tid);
        __syncthreads();

        float acc[2][8][4];
#pragma unroll
        for (int mt = 0; mt < 2; mt++)
#pragma unroll
            for (int nt = 0; nt < 8; nt++)
#pragma unroll
                for (int j = 0; j < 4; j++) acc[mt][nt][j] = 0.f;

        {
            const uint2* bp = reinterpret_cast<const uint2*>(basep + NSM_B);
            const uint32_t a_lane_off = (uint32_t)((lane & 15) * 272 + (lane >> 4) * 16);
#pragma unroll
            for (int kstep = 0; kstep < 8; kstep++) {
                uint2 bh[8];
#pragma unroll
                for (int nt = 0; nt < 8; nt++)
                    bh[nt] = bp[(kstep * 32 + warpN * 8 + nt) * 32 + lane];
#pragma unroll
                for (int mt = 0; mt < 2; mt++) {
                    uint32_t rowbase = (uint32_t)((warpM * 32 + mt * 16) * 272 + kstep * 32);
                    uint32_t ah0, ah1, ah2, ah3, al0, al1, al2, al3;
                    ldsm_x4(ah0, ah1, ah2, ah3, sbase + NSM_AHI + rowbase + a_lane_off);
                    ldsm_x4(al0, al1, al2, al3, sbase + NSM_ALO + rowbase + a_lane_off);
#pragma unroll
                    for (int nt = 0; nt < 8; nt++)
                        mma_f16(acc[mt][nt], ah0, ah1, ah2, ah3, bh[nt].x, bh[nt].y);
#pragma unroll
                    for (int nt = 0; nt < 8; nt++)
                        mma_f16(acc[mt][nt], al0, al1, al2, al3, bh[nt].x, bh[nt].y);
                }
            }
        }

        int row0 = tile * 64;
        int next = tile + gridDim.x;
        if (next < NT_NODE) load_a_regs(X, next * 64, N_NODES, tid, av);

        // fp16 store epilogue (col pairs adjacent)
#pragma unroll
        for (int mt = 0; mt < 2; mt++) {
            int rowl = warpM * 32 + mt * 16 + (lane >> 2);
#pragma unroll
            for (int nt = 0; nt < 8; nt++) {
                int col = h * 256 + warpN * 64 + nt * 8 + (lane & 3) * 2;
                int r0 = row0 + rowl;
                if (r0 < N_NODES) {
                    __half2 hv = __floats2half2_rn(acc[mt][nt][0], acc[mt][nt][1]);
                    *reinterpret_cast<__half2*>(g_P16 + (size_t)r0 * 512 + col) = hv;
                }
                int r1 = r0 + 8;
                if (r1 < N_NODES) {
                    __half2 hv = __floats2half2_rn(acc[mt][nt][2], acc[mt][nt][3]);
                    *reinterpret_cast<__half2*>(g_P16 + (size_t)r1 * 512 + col) = hv;
                }
            }
        }
        __syncthreads();
        tile = next;
    }
}

// ---------------- persistent fused edge GEMM + gate + scatter ----------------
#define SM_SRC 0
#define SM_TGT 256
#define SM_AHI 512
#define SM_ALO (512 + 64 * 272)
#define SM_B   (512 + 2 * 64 * 272)
#define SM_D   512
#define DSTRIDE 260
#define EDGE_SMEM (SM_B + 65536)

__global__ __launch_bounds__(256, 2) void edge_fused_mma(
    const float* __restrict__ A,
    const int* __restrict__ src, const int* __restrict__ tgt,
    const float* __restrict__ bf, const float* __restrict__ bs)
{
    extern __shared__ char basep[];
    const uint32_t sbase = smem_u32(basep);
    const int tid = threadIdx.x;
    const int wid = tid >> 5;
    const int lane = tid & 31;
    const int warpM = wid & 1;
    const int warpN = wid >> 1;

    int* s_src = reinterpret_cast<int*>(basep + SM_SRC);
    int* s_tgt = reinterpret_cast<int*>(basep + SM_TGT);

    // B table once per CTA
    {
        int4* dst = reinterpret_cast<int4*>(basep + SM_B);
        const int4* s = reinterpret_cast<const int4*>(g_Bfrag);
#pragma unroll
        for (int i = 0; i < 16; i++) dst[i * 256 + tid] = s[i * 256 + tid];
    }

    // epilogue constants
    const int e_tr = tid >> 5;
    const int e_tc = tid & 31;
    const float4 bfv = *reinterpret_cast<const float4*>(bf + e_tc * 4);
    const float4 bsv = *reinterpret_cast<const float4*>(bs + e_tc * 4);

    int tile = blockIdx.x;
    float4 av[8];
    int my_src = 0, my_tgt = 0;
    if (tile < NT_EDGE) {
        load_a_regs(A, tile * 64, N_EDGES, tid, av);
        if (tid < 64) {
            int r = tile * 64 + tid;
            my_src = (r < N_EDGES) ? src[r] : 0;
            my_tgt = (r < N_EDGES) ? tgt[r] : 0;
        }
    }

    while (tile < NT_EDGE) {
        store_a_split(av, basep + SM_AHI, basep + SM_ALO, tid);
        if (tid < 64) { s_src[tid] = my_src; s_tgt[tid] = my_tgt; }
        __syncthreads();

        float acc[2][8][4];
#pragma unroll
        for (int mt = 0; mt < 2; mt++)
#pragma unroll
            for (int nt = 0; nt < 8; nt++)
#pragma unroll
                for (int j = 0; j < 4; j++) acc[mt][nt][j] = 0.f;

        {
            const uint2* bp = reinterpret_cast<const uint2*>(basep + SM_B);
            const uint32_t a_lane_off = (uint32_t)((lane & 15) * 272 + (lane >> 4) * 16);
#pragma unroll
            for (int kstep = 0; kstep < 8; kstep++) {
                uint2 bh[8];
#pragma unroll
                for (int nt = 0; nt < 8; nt++)
                    bh[nt] = bp[(kstep * 32 + warpN * 8 + nt) * 32 + lane];
#pragma unroll
                for (int mt = 0; mt < 2; mt++) {
                    uint32_t rowbase = (uint32_t)((warpM * 32 + mt * 16) * 272 + kstep * 32);
                    uint32_t ah0, ah1, ah2, ah3, al0, al1, al2, al3;
                    ldsm_x4(ah0, ah1, ah2, ah3, sbase + SM_AHI + rowbase + a_lane_off);
                    ldsm_x4(al0, al1, al2, al3, sbase + SM_ALO + rowbase + a_lane_off);
#pragma unroll
                    for (int nt = 0; nt < 8; nt++)
                        mma_f16(acc[mt][nt], ah0, ah1, ah2, ah3, bh[nt].x, bh[nt].y);
#pragma unroll
                    for (int nt = 0; nt < 8; nt++)
                        mma_f16(acc[mt][nt], al0, al1, al2, al3, bh[nt].x, bh[nt].y);
                }
            }
        }
        __syncthreads();   // mainloop done; A region dead (acc live in regs)

        const int row0 = tile * 64;
        const int next = tile + gridDim.x;
        float* Dsm = reinterpret_cast<float*>(basep + SM_D);

#pragma unroll
        for (int phase = 0; phase < 2; phase++) {
            // stage rows [phase*32, phase*32+32)
            if (warpM == phase) {
#pragma unroll
                for (int mt = 0; mt < 2; mt++) {
                    int rowl = mt * 16 + (lane >> 2);
#pragma unroll
                    for (int nt = 0; nt < 8; nt++) {
                        int col = warpN * 64 + nt * 8 + (lane & 3) * 2;
                        float* p0 = Dsm + (size_t)rowl * DSTRIDE + col;
                        p0[0] = acc[mt][nt][0];
                        p0[1] = acc[mt][nt][1];
                        float* p1 = p0 + 8 * DSTRIDE;
                        p1[0] = acc[mt][nt][2];
                        p1[1] = acc[mt][nt][3];
                    }
                }
            }
            __syncthreads();

            // A-prefetch for next tile (phase 1: accs fully dead)
            if (phase == 1 && next < NT_EDGE) {
                load_a_regs(A, next * 64, N_EDGES, tid, av);
                if (tid < 64) {
                    int r = next * 64 + tid;
                    my_src = (r < N_EDGES) ? src[r] : 0;
                    my_tgt = (r < N_EDGES) ? tgt[r] : 0;
                }
            }

            // --- batch-issue ALL P gathers for this phase (no red in between ->
            //     loads overlap; breaks the gather->red serialization chain) ---
            uint4 svv[4], tvv[4];
            int sNs[4];
#pragma unroll
            for (int i = 0; i < 4; i++) {
                int grow = phase * 32 + e_tr * 4 + i;
                int sN = s_src[grow];
                int tN = s_tgt[grow];
                sNs[i] = sN;
                svv[i] = *reinterpret_cast<const uint4*>(g_P16 + (size_t)sN * 512 + e_tc * 8);
                tvv[i] = *reinterpret_cast<const uint4*>(g_P16 + (size_t)tN * 512 + 256 + e_tc * 8);
            }

            // compute gates + scatter
#pragma unroll
            for (int i = 0; i < 4; i++) {
                int lr = e_tr * 4 + i;
                int grow = phase * 32 + lr;
                int e = row0 + grow;
                if (e >= N_EDGES) break;
                const float* dp = Dsm + (size_t)lr * DSTRIDE + e_tc * 8;
                float4 d0 = *reinterpret_cast<const float4*>(dp);       // f0,s0,f1,s1
                float4 d1 = *reinterpret_cast<const float4*>(dp + 4);   // f2,s2,f3,s3

                const __half2* sh = reinterpret_cast<const __half2*>(&svv[i]);
                const __half2* th = reinterpret_cast<const __half2*>(&tvv[i]);
                float2 a0 = __half22float2(sh[0]), a1 = __half22float2(sh[1]);
                float2 a2 = __half22float2(sh[2]), a3 = __half22float2(sh[3]);
                float2 b0 = __half22float2(th[0]), b1 = __half22float2(th[1]);
                float2 b2 = __half22float2(th[2]), b3 = __half22float2(th[3]);

                float f0 = d0.x + a0.x + b0.x + bfv.x;
                float s0 = d0.y + a0.y + b0.y + bsv.x;
                float f1 = d0.z + a1.x + b1.x + bfv.y;
                float s1 = d0.w + a1.y + b1.y + bsv.y;
                float f2 = d1.x + a2.x + b2.x + bfv.z;
                float s2 = d1.y + a2.y + b2.y + bsv.z;
                float f3 = d1.z + a3.x + b3.x + bfv.w;
                float s3 = d1.w + a3.y + b3.y + bsv.w;

                float m0 = fast_sigmoid(f0) * fast_softplus(s0);
                float m1 = fast_sigmoid(f1) * fast_softplus(s1);
                float m2 = fast_sigmoid(f2) * fast_softplus(s2);
                float m3 = fast_sigmoid(f3) * fast_softplus(s3);

                float* dst = g_agg + (size_t)sNs[i] * D + e_tc * 4;
                asm volatile("red.global.add.v4.f32 [%0], {%1, %2, %3, %4};"
                             :: "l"(dst), "f"(m0), "f"(m1), "f"(m2), "f"(m3) : "memory");
            }
            __syncthreads();
        }
        tile = next;
    }
}

// ---------------- BN stats ----------------
__global__ __launch_bounds__(128) void bn_stats() {
    const int d = threadIdx.x;
    float sum = 0.f, sq = 0.f;
    for (int n = blockIdx.x; n < N_NODES; n += gridDim.x) {
        float v = g_agg[(size_t)n * D + d];
        sum += v;
        sq += v * v;
    }
    atomicAdd(&g_stats[d], sum);
    atomicAdd(&g_stats[D + d], sq);
}

// ---------------- BN apply + residual + softplus ----------------
__global__ __launch_bounds__(256) void final_kernel(
    const float* __restrict__ x, const float* __restrict__ gamma,
    const float* __restrict__ beta, float* __restrict__ out)
{
    const float invN = 1.0f / (float)N_NODES;
    for (size_t idx = (size_t)blockIdx.x * blockDim.x + threadIdx.x;
         idx < (size_t)N_NODES * D;
         idx += (size_t)gridDim.x * blockDim.x) {
        int d = (int)(idx & (D - 1));
        float mean = g_stats[d] * invN;
        float var = g_stats[D + d] * invN - mean * mean;
        float rstd = rsqrtf(var + BN_EPS);
        float a = (g_agg[idx] - mean) * rstd * gamma[d] + beta[d];
        out[idx] = fast_softplus(x[idx] + a);
    }
}

// ---------------- launch ----------------
extern "C" void kernel_launch(void* const* d_in, const int* in_sizes, int n_in,
                              void* d_out, int out_size) {
    const float* x         = (const float*)d_in[0];
    const float* edge_attr = (const float*)d_in[1];
    const int*   edge_src  = (const int*)d_in[2];
    const int*   edge_tgt  = (const int*)d_in[3];
    const float* Wf        = (const float*)d_in[4];
    const float* bf        = (const float*)d_in[5];
    const float* Ws        = (const float*)d_in[6];
    const float* bs        = (const float*)d_in[7];
    const float* gamma     = (const float*)d_in[8];
    const float* beta      = (const float*)d_in[9];
    float* out = (float*)d_out;

    static bool attr_set = false;
    if (!attr_set) {
        cudaFuncSetAttribute(edge_fused_mma, cudaFuncAttributeMaxDynamicSharedMemorySize, EDGE_SMEM);
        cudaFuncSetAttribute(node_gemm_mma, cudaFuncAttributeMaxDynamicSharedMemorySize, NODE_SMEM);
        attr_set = true;
    }

    prep_weights<<<128, 256>>>(Wf, Ws);
    zero_scratch<<<4096, 256>>>();
    {
        dim3 grid(148, 2);
        node_gemm_mma<<<grid, 256, NODE_SMEM>>>(x);
    }
    edge_fused_mma<<<296, 256, EDGE_SMEM>>>(edge_attr, edge_src, edge_tgt, bf, bs);
    bn_stats<<<512, 128>>>();
    final_kernel<<<(N_NODES * D + 255) / 256, 256>>>(x, gamma, beta, out);
}

// round 16
// speedup vs baseline: 2.0012x; 1.0075x over previous
#include <cuda_runtime.h>
#include <cuda_bf16.h>
#include <cuda_fp16.h>
#include <math.h>
#include <stdint.h>

#define N_NODES 50000
#define N_EDGES 500000
#define D 128
#define BN_EPS 1e-5f

#define NT_EDGE ((N_EDGES + 63) / 64)   // 7813
#define NT_NODE ((N_NODES + 63) / 64)   // 782

// ---------------- scratch (static device globals; no allocation) ----------------
// P in fp16, gate-interleaved: [node][j], j<256: j=2c->f1_c, j=2c+1->s1_c;
// j>=256: (j-256)=2c->f2_c, 2c+1->s2_c.   51 MB -> L2-resident.
__device__ __align__(16) __half g_P16[(size_t)N_NODES * 512];
__device__ float g_agg[(size_t)N_NODES * D];     // scatter-sum target
__device__ float g_stats[2 * D];                 // [sum | sumsq]
// Edge-B fragments for mma.sync m16n8k16 (f16), hi term, fragment-linear:
// u32 index = (((kstep*32 + ntile)*32) + lane)*2 + reg
__device__ __align__(16) uint32_t g_Bfrag[8 * 32 * 32 * 2];      // 64 KB
// Node-B fragments ([k=128][n=512], interleaved-output layout)
__device__ __align__(16) uint32_t g_B1frag[8 * 64 * 32 * 2];     // 128 KB

// node output col j -> weight value at reduction row k
__device__ __forceinline__ float b1_val(const float* Wf, const float* Ws, int k, int j) {
    int c = (j & 255) >> 1;
    int krow = (j >= 256 ? 128 : 0) + k;
    const float* W = (j & 1) ? Ws : Wf;
    return W[krow * 128 + c];
}

// ---------------- weight repack ----------------
__global__ void prep_weights(const float* __restrict__ Wf, const float* __restrict__ Ws) {
    int i = blockIdx.x * blockDim.x + threadIdx.x;
    if (i < 16384) {
        int reg   = i & 1;
        int lane  = (i >> 1) & 31;
        int ntile = (i >> 6) & 31;
        int kstep = (i >> 11) & 7;
        int k0 = kstep * 16 + (lane & 3) * 2 + reg * 8;
        int n  = ntile * 8 + (lane >> 2);
        int c  = n >> 1;
        const float* W = (n & 1) ? Ws : Wf;
        __half h0 = __float2half_rn(W[(256 + k0) * 128 + c]);
        __half h1 = __float2half_rn(W[(256 + k0 + 1) * 128 + c]);
        g_Bfrag[i] = (uint32_t)__half_as_ushort(h0) | ((uint32_t)__half_as_ushort(h1) << 16);
    }
    if (i < 32768) {
        int reg   = i & 1;
        int lane  = (i >> 1) & 31;
        int ntile = (i >> 6) & 63;
        int kstep = (i >> 12) & 7;
        int k0 = kstep * 16 + (lane & 3) * 2 + reg * 8;
        int n  = ntile * 8 + (lane >> 2);
        __half h0 = __float2half_rn(b1_val(Wf, Ws, k0, n));
        __half h1 = __float2half_rn(b1_val(Wf, Ws, k0 + 1, n));
        g_B1frag[i] = (uint32_t)__half_as_ushort(h0) | ((uint32_t)__half_as_ushort(h1) << 16);
    }
}

// ---------------- zero scratch ----------------
__global__ void zero_scratch() {
    size_t n4 = (size_t)N_NODES * D / 4;
    float4* p = reinterpret_cast<float4*>(g_agg);
    for (size_t i = blockIdx.x * blockDim.x + threadIdx.x; i < n4; i += (size_t)gridDim.x * blockDim.x)
        p[i] = make_float4(0.f, 0.f, 0.f, 0.f);
    int t = blockIdx.x * blockDim.x + threadIdx.x;
    if (t < 2 * D) g_stats[t] = 0.f;
}

// ---------------- helpers ----------------
__device__ __forceinline__ float fast_sigmoid(float x) {
    return __fdividef(1.f, 1.f + __expf(-x));
}
__device__ __forceinline__ float fast_softplus(float x) {
    return fmaxf(x, 0.f) + __logf(1.f + __expf(-fabsf(x)));
}
__device__ __forceinline__ void mma_f16(float* d, uint32_t a0, uint32_t a1, uint32_t a2,
                                        uint32_t a3, uint32_t b0, uint32_t b1) {
    asm volatile(
        "mma.sync.aligned.m16n8k16.row.col.f32.f16.f16.f32 "
        "{%0,%1,%2,%3}, {%4,%5,%6,%7}, {%8,%9}, {%0,%1,%2,%3};"
        : "+f"(d[0]), "+f"(d[1]), "+f"(d[2]), "+f"(d[3])
        : "r"(a0), "r"(a1), "r"(a2), "r"(a3), "r"(b0), "r"(b1));
}
__device__ __forceinline__ void ldsm_x4(uint32_t& a0, uint32_t& a1, uint32_t& a2, uint32_t& a3,
                                        uint32_t saddr) {
    asm volatile("ldmatrix.sync.aligned.m8n8.x4.shared.b16 {%0,%1,%2,%3}, [%4];"
                 : "=r"(a0), "=r"(a1), "=r"(a2), "=r"(a3) : "r"(saddr));
}
__device__ __forceinline__ uint32_t smem_u32(const void* p) {
    uint32_t a;
    asm("{ .reg .u64 t; cvta.to.shared.u64 t, %1; cvt.u32.u64 %0, t; }" : "=r"(a) : "l"(p));
    return a;
}

// Load a 64x128 fp32 tile into registers (8 float4/thread); zero padding beyond M.
__device__ __forceinline__ void load_a_regs(const float* __restrict__ A, int row0, int M,
                                            int tid, float4* av) {
#pragma unroll
    for (int it = 0; it < 8; it++) {
        int lin = it * 256 + tid;
        int row = lin >> 5;
        int c4 = (lin & 31) << 2;
        int e = row0 + row;
        av[it] = make_float4(0.f, 0.f, 0.f, 0.f);
        if (e < M) av[it] = *reinterpret_cast<const float4*>(A + (size_t)e * 128 + c4);
    }
}
// Convert+split registers into hi/lo fp16 smem tiles (272B row stride).
__device__ __forceinline__ void store_a_split(const float4* av, char* ahi, char* alo, int tid) {
#pragma unroll
    for (int it = 0; it < 8; it++) {
        int lin = it * 256 + tid;
        int row = lin >> 5;
        int c4 = (lin & 31) << 2;
        float4 v = av[it];
        __half h0 = __float2half_rn(v.x), h1 = __float2half_rn(v.y);
        __half h2 = __float2half_rn(v.z), h3 = __float2half_rn(v.w);
        __half l0 = __float2half_rn(v.x - __half2float(h0));
        __half l1 = __float2half_rn(v.y - __half2float(h1));
        __half l2 = __float2half_rn(v.z - __half2float(h2));
        __half l3 = __float2half_rn(v.w - __half2float(h3));
        uint2 hp, lp;
        hp.x = (uint32_t)__half_as_ushort(h0) | ((uint32_t)__half_as_ushort(h1) << 16);
        hp.y = (uint32_t)__half_as_ushort(h2) | ((uint32_t)__half_as_ushort(h3) << 16);
        lp.x = (uint32_t)__half_as_ushort(l0) | ((uint32_t)__half_as_ushort(l1) << 16);
        lp.y = (uint32_t)__half_as_ushort(l2) | ((uint32_t)__half_as_ushort(l3) << 16);
        int off = row * 272 + c4 * 2;
        *reinterpret_cast<uint2*>(ahi + off) = hp;
        *reinterpret_cast<uint2*>(alo + off) = lp;
    }
}

// ---------------- persistent node GEMM: g_P16[M,512] = fp16(x @ B1) ----------------
#define NSM_AHI 0
#define NSM_ALO (64 * 272)
#define NSM_B   (2 * 64 * 272)
#define NODE_SMEM (NSM_B + 65536)

__global__ __launch_bounds__(256, 2) void node_gemm_mma(const float* __restrict__ X)
{
    extern __shared__ char basep[];
    const uint32_t sbase = smem_u32(basep);
    const int tid = threadIdx.x;
    const int wid = tid >> 5;
    const int lane = tid & 31;
    const int h = blockIdx.y;
    const int warpM = wid & 1;
    const int warpN = wid >> 1;

    // B slice once
    {
        int4* dst = reinterpret_cast<int4*>(basep + NSM_B);
        const int4* s = reinterpret_cast<const int4*>(g_B1frag);
#pragma unroll
        for (int it = 0; it < 16; it++) {
            int idx = it * 256 + tid;
            int kstep = idx >> 9;
            int within = idx & 511;
            dst[idx] = s[kstep * 1024 + h * 512 + within];
        }
    }

    int tile = blockIdx.x;
    float4 av[8];
    if (tile < NT_NODE) load_a_regs(X, tile * 64, N_NODES, tid, av);

    while (tile < NT_NODE) {
        store_a_split(av, basep + NSM_AHI, basep + NSM_ALO, tid);
        __syncthreads();

        float acc[2][8][4];
#pragma unroll
        for (int mt = 0; mt < 2; mt++)
#pragma unroll
            for (int nt = 0; nt < 8; nt++)
#pragma unroll
                for (int j = 0; j < 4; j++) acc[mt][nt][j] = 0.f;

        {
            const uint2* bp = reinterpret_cast<const uint2*>(basep + NSM_B);
            const uint32_t a_lane_off = (uint32_t)((lane & 15) * 272 + (lane >> 4) * 16);
#pragma unroll
            for (int kstep = 0; kstep < 8; kstep++) {
                uint2 bh[8];
#pragma unroll
                for (int nt = 0; nt < 8; nt++)
                    bh[nt] = bp[(kstep * 32 + warpN * 8 + nt) * 32 + lane];
#pragma unroll
                for (int mt = 0; mt < 2; mt++) {
                    uint32_t rowbase = (uint32_t)((warpM * 32 + mt * 16) * 272 + kstep * 32);
                    uint32_t ah0, ah1, ah2, ah3, al0, al1, al2, al3;
                    ldsm_x4(ah0, ah1, ah2, ah3, sbase + NSM_AHI + rowbase + a_lane_off);
                    ldsm_x4(al0, al1, al2, al3, sbase + NSM_ALO + rowbase + a_lane_off);
#pragma unroll
                    for (int nt = 0; nt < 8; nt++)
                        mma_f16(acc[mt][nt], ah0, ah1, ah2, ah3, bh[nt].x, bh[nt].y);
#pragma unroll
                    for (int nt = 0; nt < 8; nt++)
                        mma_f16(acc[mt][nt], al0, al1, al2, al3, bh[nt].x, bh[nt].y);
                }
            }
        }

        int row0 = tile * 64;
        int next = tile + gridDim.x;
        if (next < NT_NODE) load_a_regs(X, next * 64, N_NODES, tid, av);

        // fp16 store epilogue (col pairs adjacent)
#pragma unroll
        for (int mt = 0; mt < 2; mt++) {
            int rowl = warpM * 32 + mt * 16 + (lane >> 2);
#pragma unroll
            for (int nt = 0; nt < 8; nt++) {
                int col = h * 256 + warpN * 64 + nt * 8 + (lane & 3) * 2;
                int r0 = row0 + rowl;
                if (r0 < N_NODES) {
                    __half2 hv = __floats2half2_rn(acc[mt][nt][0], acc[mt][nt][1]);
                    *reinterpret_cast<__half2*>(g_P16 + (size_t)r0 * 512 + col) = hv;
                }
                int r1 = r0 + 8;
                if (r1 < N_NODES) {
                    __half2 hv = __floats2half2_rn(acc[mt][nt][2], acc[mt][nt][3]);
                    *reinterpret_cast<__half2*>(g_P16 + (size_t)r1 * 512 + col) = hv;
                }
            }
        }
        __syncthreads();
        tile = next;
    }
}

// ---------------- persistent fused edge GEMM + gate + scatter ----------------
#define SM_SRC 0
#define SM_TGT 256
#define SM_AHI 512
#define SM_ALO (512 + 64 * 272)
#define SM_B   (512 + 2 * 64 * 272)
#define SM_D   512
#define DSTRIDE 260
#define EDGE_SMEM (SM_B + 65536)

__global__ __launch_bounds__(256, 2) void edge_fused_mma(
    const float* __restrict__ A,
    const int* __restrict__ src, const int* __restrict__ tgt,
    const float* __restrict__ bf, const float* __restrict__ bs)
{
    extern __shared__ char basep[];
    const uint32_t sbase = smem_u32(basep);
    const int tid = threadIdx.x;
    const int wid = tid >> 5;
    const int lane = tid & 31;
    const int warpM = wid & 1;
    const int warpN = wid >> 1;

    int* s_src = reinterpret_cast<int*>(basep + SM_SRC);
    int* s_tgt = reinterpret_cast<int*>(basep + SM_TGT);

    // B table once per CTA
    {
        int4* dst = reinterpret_cast<int4*>(basep + SM_B);
        const int4* s = reinterpret_cast<const int4*>(g_Bfrag);
#pragma unroll
        for (int i = 0; i < 16; i++) dst[i * 256 + tid] = s[i * 256 + tid];
    }

    // epilogue constants
    const int e_tr = tid >> 5;
    const int e_tc = tid & 31;
    const float4 bfv = *reinterpret_cast<const float4*>(bf + e_tc * 4);
    const float4 bsv = *reinterpret_cast<const float4*>(bs + e_tc * 4);

    int tile = blockIdx.x;
    float4 av[8];
    int my_src = 0, my_tgt = 0;
    if (tile < NT_EDGE) {
        load_a_regs(A, tile * 64, N_EDGES, tid, av);
        if (tid < 64) {
            int r = tile * 64 + tid;
            my_src = (r < N_EDGES) ? src[r] : 0;
            my_tgt = (r < N_EDGES) ? tgt[r] : 0;
        }
    }

    while (tile < NT_EDGE) {
        store_a_split(av, basep + SM_AHI, basep + SM_ALO, tid);
        if (tid < 64) { s_src[tid] = my_src; s_tgt[tid] = my_tgt; }
        __syncthreads();

        float acc[2][8][4];
#pragma unroll
        for (int mt = 0; mt < 2; mt++)
#pragma unroll
            for (int nt = 0; nt < 8; nt++)
#pragma unroll
                for (int j = 0; j < 4; j++) acc[mt][nt][j] = 0.f;

        {
            const uint2* bp = reinterpret_cast<const uint2*>(basep + SM_B);
            const uint32_t a_lane_off = (uint32_t)((lane & 15) * 272 + (lane >> 4) * 16);
#pragma unroll
            for (int kstep = 0; kstep < 8; kstep++) {
                uint2 bh[8];
#pragma unroll
                for (int nt = 0; nt < 8; nt++)
                    bh[nt] = bp[(kstep * 32 + warpN * 8 + nt) * 32 + lane];
#pragma unroll
                for (int mt = 0; mt < 2; mt++) {
                    uint32_t rowbase = (uint32_t)((warpM * 32 + mt * 16) * 272 + kstep * 32);
                    uint32_t ah0, ah1, ah2, ah3, al0, al1, al2, al3;
                    ldsm_x4(ah0, ah1, ah2, ah3, sbase + SM_AHI + rowbase + a_lane_off);
                    ldsm_x4(al0, al1, al2, al3, sbase + SM_ALO + rowbase + a_lane_off);
#pragma unroll
                    for (int nt = 0; nt < 8; nt++)
                        mma_f16(acc[mt][nt], ah0, ah1, ah2, ah3, bh[nt].x, bh[nt].y);
#pragma unroll
                    for (int nt = 0; nt < 8; nt++)
                        mma_f16(acc[mt][nt], al0, al1, al2, al3, bh[nt].x, bh[nt].y);
                }
            }
        }
        __syncthreads();   // mainloop done; A region dead (acc live in regs)

        const int row0 = tile * 64;
        const int next = tile + gridDim.x;
        float* Dsm = reinterpret_cast<float*>(basep + SM_D);

#pragma unroll
        for (int phase = 0; phase < 2; phase++) {
            // stage rows [phase*32, phase*32+32)
            if (warpM == phase) {
#pragma unroll
                for (int mt = 0; mt < 2; mt++) {
                    int rowl = mt * 16 + (lane >> 2);
#pragma unroll
                    for (int nt = 0; nt < 8; nt++) {
                        int col = warpN * 64 + nt * 8 + (lane & 3) * 2;
                        float* p0 = Dsm + (size_t)rowl * DSTRIDE + col;
                        p0[0] = acc[mt][nt][0];
                        p0[1] = acc[mt][nt][1];
                        float* p1 = p0 + 8 * DSTRIDE;
                        p1[0] = acc[mt][nt][2];
                        p1[1] = acc[mt][nt][3];
                    }
                }
            }
            __syncthreads();

            // A-prefetch for next tile (phase 1: accs fully dead)
            if (phase == 1 && next < NT_EDGE) {
                load_a_regs(A, next * 64, N_EDGES, tid, av);
                if (tid < 64) {
                    int r = next * 64 + tid;
                    my_src = (r < N_EDGES) ? src[r] : 0;
                    my_tgt = (r < N_EDGES) ? tgt[r] : 0;
                }
            }

            // --- batch-issue ALL P gathers for this phase (no red in between ->
            //     loads overlap; breaks the gather->red serialization chain) ---
            uint4 svv[4], tvv[4];
            int sNs[4];
#pragma unroll
            for (int i = 0; i < 4; i++) {
                int grow = phase * 32 + e_tr * 4 + i;
                int sN = s_src[grow];
                int tN = s_tgt[grow];
                sNs[i] = sN;
                svv[i] = *reinterpret_cast<const uint4*>(g_P16 + (size_t)sN * 512 + e_tc * 8);
                tvv[i] = *reinterpret_cast<const uint4*>(g_P16 + (size_t)tN * 512 + 256 + e_tc * 8);
            }

            // compute gates + scatter
#pragma unroll
            for (int i = 0; i < 4; i++) {
                int lr = e_tr * 4 + i;
                int grow = phase * 32 + lr;
                int e = row0 + grow;
                if (e >= N_EDGES) break;
                const float* dp = Dsm + (size_t)lr * DSTRIDE + e_tc * 8;
                float4 d0 = *reinterpret_cast<const float4*>(dp);       // f0,s0,f1,s1
                float4 d1 = *reinterpret_cast<const float4*>(dp + 4);   // f2,s2,f3,s3

                const __half2* sh = reinterpret_cast<const __half2*>(&svv[i]);
                const __half2* th = reinterpret_cast<const __half2*>(&tvv[i]);
                float2 a0 = __half22float2(sh[0]), a1 = __half22float2(sh[1]);
                float2 a2 = __half22float2(sh[2]), a3 = __half22float2(sh[3]);
                float2 b0 = __half22float2(th[0]), b1 = __half22float2(th[1]);
                float2 b2 = __half22float2(th[2]), b3 = __half22float2(th[3]);

                float f0 = d0.x + a0.x + b0.x + bfv.x;
                float s0 = d0.y + a0.y + b0.y + bsv.x;
                float f1 = d0.z + a1.x + b1.x + bfv.y;
                float s1 = d0.w + a1.y + b1.y + bsv.y;
                float f2 = d1.x + a2.x + b2.x + bfv.z;
                float s2 = d1.y + a2.y + b2.y + bsv.z;
                float f3 = d1.z + a3.x + b3.x + bfv.w;
                float s3 = d1.w + a3.y + b3.y + bsv.w;

                float m0 = fast_sigmoid(f0) * fast_softplus(s0);
                float m1 = fast_sigmoid(f1) * fast_softplus(s1);
                float m2 = fast_sigmoid(f2) * fast_softplus(s2);
                float m3 = fast_sigmoid(f3) * fast_softplus(s3);

                float* dst = g_agg + (size_t)sNs[i] * D + e_tc * 4;
                asm volatile("red.global.add.v4.f32 [%0], {%1, %2, %3, %4};"
                             :: "l"(dst), "f"(m0), "f"(m1), "f"(m2), "f"(m3) : "memory");
            }
            __syncthreads();
        }
        tile = next;
    }
}

// ---------------- BN stats ----------------
__global__ __launch_bounds__(128) void bn_stats() {
    const int d = threadIdx.x;
    float sum = 0.f, sq = 0.f;
    for (int n = blockIdx.x; n < N_NODES; n += gridDim.x) {
        float v = g_agg[(size_t)n * D + d];
        sum += v;
        sq += v * v;
    }
    atomicAdd(&g_stats[d], sum);
    atomicAdd(&g_stats[D + d], sq);
}

// ---------------- BN apply + residual + softplus ----------------
__global__ __launch_bounds__(256) void final_kernel(
    const float* __restrict__ x, const float* __restrict__ gamma,
    const float* __restrict__ beta, float* __restrict__ out)
{
    const float invN = 1.0f / (float)N_NODES;
    for (size_t idx = (size_t)blockIdx.x * blockDim.x + threadIdx.x;
         idx < (size_t)N_NODES * D;
         idx += (size_t)gridDim.x * blockDim.x) {
        int d = (int)(idx & (D - 1));
        float mean = g_stats[d] * invN;
        float var = g_stats[D + d] * invN - mean * mean;
        float rstd = rsqrtf(var + BN_EPS);
        float a = (g_agg[idx] - mean) * rstd * gamma[d] + beta[d];
        out[idx] = fast_softplus(x[idx] + a);
    }
}

// ---------------- launch ----------------
extern "C" void kernel_launch(void* const* d_in, const int* in_sizes, int n_in,
                              void* d_out, int out_size) {
    const float* x         = (const float*)d_in[0];
    const float* edge_attr = (const float*)d_in[1];
    const int*   edge_src  = (const int*)d_in[2];
    const int*   edge_tgt  = (const int*)d_in[3];
    const float* Wf        = (const float*)d_in[4];
    const float* bf        = (const float*)d_in[5];
    const float* Ws        = (const float*)d_in[6];
    const float* bs        = (const float*)d_in[7];
    const float* gamma     = (const float*)d_in[8];
    const float* beta      = (const float*)d_in[9];
    float* out = (float*)d_out;

    static bool attr_set = false;
    if (!attr_set) {
        cudaFuncSetAttribute(edge_fused_mma, cudaFuncAttributeMaxDynamicSharedMemorySize, EDGE_SMEM);
        cudaFuncSetAttribute(node_gemm_mma, cudaFuncAttributeMaxDynamicSharedMemorySize, NODE_SMEM);
        attr_set = true;
    }

    prep_weights<<<128, 256>>>(Wf, Ws);
    zero_scratch<<<4096, 256>>>();
    {
        dim3 grid(148, 2);
        node_gemm_mma<<<grid, 256, NODE_SMEM>>>(x);
    }
    edge_fused_mma<<<296, 256, EDGE_SMEM>>>(edge_attr, edge_src, edge_tgt, bf, bs);
    bn_stats<<<512, 128>>>();
    final_kernel<<<(N_NODES * D + 255) / 256, 256>>>(x, gamma, beta, out);
}